// round 2
// baseline (speedup 1.0000x reference)
#include <cuda_runtime.h>
#include <cuda_bf16.h>

// Problem constants
#define BATCH     16
#define IMG       56
#define CDIM      384
#define NHEADS    12
#define HDIM      32
#define NTOK      49          // 7*7 tokens per window
#define WIN_TOT   1024        // 16 * 8 * 8
#define M_TOT     50176       // WIN_TOT * NTOK
#define KDIM      384
#define NQKV      1152

// Scratch (allocation-free rule: static device globals)
__device__ float g_qkv[(size_t)M_TOT * NQKV];   // [m][3*C] : q|k|v per token
__device__ float g_att[(size_t)M_TOT * CDIM];   // attention output, pre-proj

// roll(-3,-3) + window-partition gather offset for row m = win*49 + tok.
// Same formula works for the inverse scatter (merge + roll(+3,+3)).
__device__ __forceinline__ int pix_offset(int m) {
    int win = m / 49;
    int tok = m - win * 49;
    int b  = win >> 6;
    int wi = win & 63;
    int wy = wi >> 3, wx = wi & 7;
    int ty = tok / 7, tx = tok - ty * 7;
    int h = wy * 7 + ty + 3; if (h >= IMG) h -= IMG;
    int w = wx * 7 + tx + 3; if (w >= IMG) w -= IMG;
    return ((b * IMG + h) * IMG + w) * CDIM;
}

// ---------------------------------------------------------------------------
// QKV GEMM: out[m][n] = sum_k X[m][k] * Wqkv[n][k] + bqkv[n]
// A is gathered from x with the roll+partition mapping.
// 64x64 tile, BK=16, 256 threads, 4x4 per thread.
// ---------------------------------------------------------------------------
__global__ __launch_bounds__(256) void qkv_gemm_kernel(
    const float* __restrict__ x, const float* __restrict__ w,
    const float* __restrict__ bias)
{
    __shared__ float As[16][68];
    __shared__ float Bs[16][68];

    int tid = threadIdx.x;
    int tx = tid & 15, ty = tid >> 4;
    int row = tid >> 2, kc = tid & 3;

    int m = blockIdx.y * 64 + row;
    const float* aPtr = x + pix_offset(m) + kc * 4;
    int n = blockIdx.x * 64 + row;
    const float* bPtr = w + (size_t)n * KDIM + kc * 4;

    float acc[4][4] = {};

    for (int kk = 0; kk < KDIM; kk += 16) {
        float4 av = *(const float4*)(aPtr + kk);
        float4 bv = *(const float4*)(bPtr + kk);
        __syncthreads();
        As[kc*4+0][row] = av.x; As[kc*4+1][row] = av.y;
        As[kc*4+2][row] = av.z; As[kc*4+3][row] = av.w;
        Bs[kc*4+0][row] = bv.x; Bs[kc*4+1][row] = bv.y;
        Bs[kc*4+2][row] = bv.z; Bs[kc*4+3][row] = bv.w;
        __syncthreads();
        #pragma unroll
        for (int k = 0; k < 16; k++) {
            float4 a4 = *(const float4*)&As[k][ty*4];
            float4 b4 = *(const float4*)&Bs[k][tx*4];
            float ar[4] = {a4.x, a4.y, a4.z, a4.w};
            float br[4] = {b4.x, b4.y, b4.z, b4.w};
            #pragma unroll
            for (int i = 0; i < 4; i++)
                #pragma unroll
                for (int j = 0; j < 4; j++)
                    acc[i][j] += ar[i] * br[j];
        }
    }

    int m0 = blockIdx.y * 64 + ty * 4;
    int n0 = blockIdx.x * 64 + tx * 4;
    float4 bb = *(const float4*)(bias + n0);
    #pragma unroll
    for (int i = 0; i < 4; i++) {
        float4 r;
        r.x = acc[i][0] + bb.x; r.y = acc[i][1] + bb.y;
        r.z = acc[i][2] + bb.z; r.w = acc[i][3] + bb.w;
        *(float4*)(g_qkv + (size_t)(m0 + i) * NQKV + n0) = r;
    }
}

// ---------------------------------------------------------------------------
// Attention: one block per (head, window). 64 threads, threads 0..48 own rows.
// scores = q*scale @ k^T + rel_pos_bias + shift_mask ; softmax ; @ v
// ---------------------------------------------------------------------------
__global__ __launch_bounds__(64) void attn_kernel(
    const float* __restrict__ table)
{
    __shared__ float4 ksh[NTOK * 8];
    __shared__ float4 vsh[NTOK * 8];
    __shared__ float  S[NTOK * NTOK];
    __shared__ int    sid[NTOK];

    int head = blockIdx.x;
    int win  = blockIdx.y;
    int tid  = threadIdx.x;

    size_t base = (size_t)win * NTOK * NQKV + head * HDIM;

    // cooperative load of K and V tiles (49 x 32 each)
    for (int f = tid; f < NTOK * 8; f += 64) {
        int t = f >> 3, dc = f & 7;
        size_t off = base + (size_t)t * NQKV + dc * 4;
        ksh[f] = *(const float4*)(g_qkv + off + 384);
        vsh[f] = *(const float4*)(g_qkv + off + 768);
    }
    if (tid < NTOK) {
        // shifted-window region id (pH=pW=56, wh=ww=7, sh=sw=3)
        int wy = (win & 63) >> 3, wx = win & 7;
        int ty = tid / 7, tx = tid - ty * 7;
        int hreg = (wy < 7) ? 0 : ((ty < 4) ? 1 : 2);
        int wreg = (wx < 7) ? 0 : ((tx < 4) ? 1 : 2);
        sid[tid] = hreg * 3 + wreg;
    }
    __syncthreads();

    int r = tid;
    if (r < NTOK) {
        const float sc = 0.17677669529663687f;  // 32^-0.5
        float4 q[8];
        const float* qp = g_qkv + base + (size_t)r * NQKV;
        #pragma unroll
        for (int dc = 0; dc < 8; dc++) {
            float4 v = *(const float4*)(qp + dc * 4);
            q[dc] = make_float4(v.x * sc, v.y * sc, v.z * sc, v.w * sc);
        }
        int iy = r / 7, ix = r - iy * 7;
        int myid = sid[r];
        float* srow = S + r * NTOK;
        float maxv = -1e30f;
        for (int mc = 0; mc < NTOK; mc++) {
            const float4* kp = &ksh[mc * 8];
            float dot = 0.f;
            #pragma unroll
            for (int dc = 0; dc < 8; dc++) {
                float4 kv = kp[dc];
                dot += q[dc].x * kv.x + q[dc].y * kv.y
                     + q[dc].z * kv.z + q[dc].w * kv.w;
            }
            int jy = mc / 7, jx = mc - jy * 7;
            float bval = table[((iy - jy + 6) * 13 + (ix - jx + 6)) * NHEADS + head];
            float val = dot + bval + ((sid[mc] != myid) ? -100.0f : 0.0f);
            srow[mc] = val;
            maxv = fmaxf(maxv, val);
        }
        float sum = 0.f;
        for (int mc = 0; mc < NTOK; mc++) {
            float e = __expf(srow[mc] - maxv);
            srow[mc] = e;
            sum += e;
        }
        float inv = 1.0f / sum;
        float o[32] = {};
        for (int mc = 0; mc < NTOK; mc++) {
            float p = srow[mc] * inv;
            const float4* vp = &vsh[mc * 8];
            #pragma unroll
            for (int dc = 0; dc < 8; dc++) {
                float4 vv = vp[dc];
                o[dc*4+0] += p * vv.x; o[dc*4+1] += p * vv.y;
                o[dc*4+2] += p * vv.z; o[dc*4+3] += p * vv.w;
            }
        }
        float* op = g_att + (size_t)(win * NTOK + r) * CDIM + head * HDIM;
        #pragma unroll
        for (int dc = 0; dc < 8; dc++)
            *(float4*)(op + dc * 4) =
                make_float4(o[dc*4], o[dc*4+1], o[dc*4+2], o[dc*4+3]);
    }
}

// ---------------------------------------------------------------------------
// Proj GEMM: out[pix(m)][c] = sum_k Att[m][k] * Wp[c][k] + bp[c]
// Epilogue scatters through window-merge + roll(+3,+3).
// ---------------------------------------------------------------------------
__global__ __launch_bounds__(256) void proj_gemm_kernel(
    const float* __restrict__ w, const float* __restrict__ bias,
    float* __restrict__ out)
{
    __shared__ float As[16][68];
    __shared__ float Bs[16][68];

    int tid = threadIdx.x;
    int tx = tid & 15, ty = tid >> 4;
    int row = tid >> 2, kc = tid & 3;

    int m = blockIdx.y * 64 + row;
    const float* aPtr = g_att + (size_t)m * CDIM + kc * 4;
    int n = blockIdx.x * 64 + row;
    const float* bPtr = w + (size_t)n * KDIM + kc * 4;

    float acc[4][4] = {};

    for (int kk = 0; kk < KDIM; kk += 16) {
        float4 av = *(const float4*)(aPtr + kk);
        float4 bv = *(const float4*)(bPtr + kk);
        __syncthreads();
        As[kc*4+0][row] = av.x; As[kc*4+1][row] = av.y;
        As[kc*4+2][row] = av.z; As[kc*4+3][row] = av.w;
        Bs[kc*4+0][row] = bv.x; Bs[kc*4+1][row] = bv.y;
        Bs[kc*4+2][row] = bv.z; Bs[kc*4+3][row] = bv.w;
        __syncthreads();
        #pragma unroll
        for (int k = 0; k < 16; k++) {
            float4 a4 = *(const float4*)&As[k][ty*4];
            float4 b4 = *(const float4*)&Bs[k][tx*4];
            float ar[4] = {a4.x, a4.y, a4.z, a4.w};
            float br[4] = {b4.x, b4.y, b4.z, b4.w};
            #pragma unroll
            for (int i = 0; i < 4; i++)
                #pragma unroll
                for (int j = 0; j < 4; j++)
                    acc[i][j] += ar[i] * br[j];
        }
    }

    int m0 = blockIdx.y * 64 + ty * 4;
    int n0 = blockIdx.x * 64 + tx * 4;
    float4 bb = *(const float4*)(bias + n0);
    #pragma unroll
    for (int i = 0; i < 4; i++) {
        int dst = pix_offset(m0 + i);   // same map inverts the gather
        float4 r;
        r.x = acc[i][0] + bb.x; r.y = acc[i][1] + bb.y;
        r.z = acc[i][2] + bb.z; r.w = acc[i][3] + bb.w;
        *(float4*)(out + (size_t)dst + n0) = r;
    }
}

extern "C" void kernel_launch(void* const* d_in, const int* in_sizes, int n_in,
                              void* d_out, int out_size) {
    const float* x     = (const float*)d_in[0];
    const float* wqkv  = (const float*)d_in[1];
    const float* bqkv  = (const float*)d_in[2];
    const float* wproj = (const float*)d_in[3];
    const float* bproj = (const float*)d_in[4];
    const float* table = (const float*)d_in[5];
    float* out = (float*)d_out;

    qkv_gemm_kernel<<<dim3(NQKV / 64, M_TOT / 64), 256>>>(x, wqkv, bqkv);
    attn_kernel<<<dim3(NHEADS, WIN_TOT), 64>>>(table);
    proj_gemm_kernel<<<dim3(CDIM / 64, M_TOT / 64), 256>>>(wproj, bproj, out);
}

// round 4
// speedup vs baseline: 2.8184x; 2.8184x over previous
#include <cuda_runtime.h>
#include <cuda_fp16.h>
#include <cstdint>

// Problem constants
#define BATCH     16
#define IMG       56
#define CDIM      384
#define NHEADS    12
#define HDIM      32
#define NTOK      49
#define WIN_TOT   1024
#define M_TOT     50176
#define KDIM      384
#define NQKV      1152

#define TILE_MN   128
#define KC        64          // K elems per chunk; 64 fp16 = 128B row
#define NCHUNK    6           // 384/64

// Scratch
__device__ float g_qkv[(size_t)M_TOT * NQKV];
__device__ float g_att[(size_t)M_TOT * CDIM];

__device__ __forceinline__ uint32_t smem_u32(const void* p) {
    uint32_t a;
    asm("{ .reg .u64 t; cvta.to.shared.u64 t, %1; cvt.u32.u64 %0, t; }"
        : "=r"(a) : "l"(p));
    return a;
}

// roll(-3,-3) + window-partition gather offset for row m = win*49 + tok.
__device__ __forceinline__ int pix_offset(int m) {
    int win = m / 49;
    int tok = m - win * 49;
    int b  = win >> 6;
    int wi = win & 63;
    int wy = wi >> 3, wx = wi & 7;
    int ty = tok / 7, tx = tok - ty * 7;
    int h = wy * 7 + ty + 3; if (h >= IMG) h -= IMG;
    int w = wx * 7 + tx + 3; if (w >= IMG) w -= IMG;
    return ((b * IMG + h) * IMG + w) * CDIM;
}

union H2U { __half2 h; uint32_t u; };

__device__ __forceinline__ uint32_t pack2(float x, float y) {
    H2U v; v.h = __floats2half2_rn(x, y);
    return v.u;
}

__device__ __forceinline__ void ldmatrix_x4(uint32_t addr, uint32_t& r0,
                                            uint32_t& r1, uint32_t& r2, uint32_t& r3) {
    asm volatile("ldmatrix.sync.aligned.m8n8.x4.shared.b16 {%0,%1,%2,%3}, [%4];"
                 : "=r"(r0), "=r"(r1), "=r"(r2), "=r"(r3) : "r"(addr));
}

__device__ __forceinline__ void mma16816(float* d, const uint32_t* a, const uint32_t* b) {
    asm volatile(
        "mma.sync.aligned.m16n8k16.row.col.f32.f16.f16.f32 "
        "{%0,%1,%2,%3}, {%4,%5,%6,%7}, {%8,%9}, {%0,%1,%2,%3};"
        : "+f"(d[0]), "+f"(d[1]), "+f"(d[2]), "+f"(d[3])
        : "r"(a[0]), "r"(a[1]), "r"(a[2]), "r"(a[3]), "r"(b[0]), "r"(b[1]));
}

// ---------------------------------------------------------------------------
// fp16 tensor-core GEMM: Out[m][n] = A[m][:] . W[n][:] + bias[n]
// CTA 128x128, 8 warps (2x4), warp tile 64x32.
// GATHER_A: A rows gathered from x via pix_offset (roll + window partition).
// SCATTER_OUT: output rows scattered via pix_offset (merge + roll back).
// ---------------------------------------------------------------------------
template<bool GATHER_A, bool SCATTER_OUT>
__global__ __launch_bounds__(256) void gemm_mma_kernel(
    const float* __restrict__ Ain, const float* __restrict__ W,
    const float* __restrict__ bias, float* __restrict__ Out,
    int ldA, int ldOut)
{
    __shared__ __align__(128) uint32_t smem[8192];   // 32KB: A 16KB | B 16KB
    uint32_t sb  = smem_u32(smem);
    uint32_t sbB = sb + 16384;

    int tid  = threadIdx.x;
    int lane = tid & 31, wid = tid >> 5;
    int warpM = wid >> 2, warpN = wid & 3;           // 2 x 4
    int tileM0 = blockIdx.y * TILE_MN;
    int n0 = blockIdx.x * TILE_MN;

    float acc[4][4][4] = {};                         // [mt][nt][reg]

    // ldmatrix per-thread geometry
    int rowA = warpM * 64 + (lane & 15);
    int kA   = (lane >> 4) * 8;
    uint32_t xa = (uint32_t)((rowA & 7) << 4);
    int rowB = warpN * 32 + (lane & 7) + ((lane >> 4) << 3);
    int kB   = ((lane >> 3) & 1) * 8;
    uint32_t xb = (uint32_t)((rowB & 7) << 4);

    // loader geometry: 16B (8 half) per thread-slot
    int lr = tid >> 3;        // base row (0..31), +32 per iter
    int lc = tid & 7;         // 16B chunk within 128B row

    for (int c = 0; c < NCHUNK; ++c) {
        // prefetch + convert (overlaps previous chunk's MMAs; no smem touch)
        uint32_t pa[4][4], pb[4][4];
        #pragma unroll
        for (int it = 0; it < 4; ++it) {
            int r = lr + it * 32;
            const float* ap = GATHER_A
                ? Ain + pix_offset(tileM0 + r) + c * KC + lc * 8
                : Ain + (size_t)(tileM0 + r) * ldA + c * KC + lc * 8;
            float4 a0 = *(const float4*)ap;
            float4 a1 = *(const float4*)(ap + 4);
            pa[it][0] = pack2(a0.x, a0.y); pa[it][1] = pack2(a0.z, a0.w);
            pa[it][2] = pack2(a1.x, a1.y); pa[it][3] = pack2(a1.z, a1.w);
            const float* bp = W + (size_t)(n0 + r) * KDIM + c * KC + lc * 8;
            float4 b0 = *(const float4*)bp;
            float4 b1 = *(const float4*)(bp + 4);
            pb[it][0] = pack2(b0.x, b0.y); pb[it][1] = pack2(b0.z, b0.w);
            pb[it][2] = pack2(b1.x, b1.y); pb[it][3] = pack2(b1.z, b1.w);
        }
        __syncthreads();      // previous chunk's MMAs done reading smem
        #pragma unroll
        for (int it = 0; it < 4; ++it) {
            int r = lr + it * 32;
            uint32_t off = ((uint32_t)(r * 128 + lc * 16)) ^ ((uint32_t)((r & 7) << 4));
            *(uint4*)((char*)smem + off) =
                make_uint4(pa[it][0], pa[it][1], pa[it][2], pa[it][3]);
            *(uint4*)((char*)smem + 16384 + off) =
                make_uint4(pb[it][0], pb[it][1], pb[it][2], pb[it][3]);
        }
        __syncthreads();

        // compute: 4 k16 steps
        #pragma unroll
        for (int ks = 0; ks < 4; ++ks) {
            uint32_t a[4][4], b[4][2];
            #pragma unroll
            for (int mt = 0; mt < 4; ++mt) {
                uint32_t addr = sb + ((uint32_t)((rowA + mt * 16) * 128 + ks * 32 + kA * 2) ^ xa);
                ldmatrix_x4(addr, a[mt][0], a[mt][1], a[mt][2], a[mt][3]);
            }
            #pragma unroll
            for (int p = 0; p < 2; ++p) {
                uint32_t addr = sbB + ((uint32_t)((rowB + p * 16) * 128 + ks * 32 + kB * 2) ^ xb);
                uint32_t r0, r1, r2, r3;
                ldmatrix_x4(addr, r0, r1, r2, r3);
                b[2 * p][0] = r0; b[2 * p][1] = r1;
                b[2 * p + 1][0] = r2; b[2 * p + 1][1] = r3;
            }
            #pragma unroll
            for (int mt = 0; mt < 4; ++mt)
                #pragma unroll
                for (int nt = 0; nt < 4; ++nt)
                    mma16816(acc[mt][nt], a[mt], b[nt]);
        }
    }

    // epilogue: bias + direct/scattered store
    #pragma unroll
    for (int mt = 0; mt < 4; ++mt) {
        int m = tileM0 + warpM * 64 + mt * 16 + (lane >> 2);
        float* r0;
        float* r1;
        if (SCATTER_OUT) {
            r0 = Out + pix_offset(m);
            r1 = Out + pix_offset(m + 8);
        } else {
            r0 = Out + (size_t)m * ldOut;
            r1 = Out + (size_t)(m + 8) * ldOut;
        }
        #pragma unroll
        for (int nt = 0; nt < 4; ++nt) {
            int n = n0 + warpN * 32 + nt * 8 + (lane & 3) * 2;
            float bx = __ldg(bias + n), by = __ldg(bias + n + 1);
            float2 o0 = make_float2(acc[mt][nt][0] + bx, acc[mt][nt][1] + by);
            float2 o1 = make_float2(acc[mt][nt][2] + bx, acc[mt][nt][3] + by);
            *(float2*)(r0 + n) = o0;
            *(float2*)(r1 + n) = o1;
        }
    }
}

// ---------------------------------------------------------------------------
// Attention: one block per (head, window), fp32.
// ---------------------------------------------------------------------------
__global__ __launch_bounds__(64) void attn_kernel(const float* __restrict__ table)
{
    __shared__ float4 ksh[NTOK * 8];
    __shared__ float4 vsh[NTOK * 8];
    __shared__ float  S[NTOK * NTOK];
    __shared__ int    sid[NTOK];

    int head = blockIdx.x;
    int win  = blockIdx.y;
    int tid  = threadIdx.x;

    size_t base = (size_t)win * NTOK * NQKV + head * HDIM;

    for (int f = tid; f < NTOK * 8; f += 64) {
        int t = f >> 3, dc = f & 7;
        size_t off = base + (size_t)t * NQKV + dc * 4;
        ksh[f] = *(const float4*)(g_qkv + off + 384);
        vsh[f] = *(const float4*)(g_qkv + off + 768);
    }
    if (tid < NTOK) {
        int wy = (win & 63) >> 3, wx = win & 7;
        int ty = tid / 7, tx = tid - ty * 7;
        int hreg = (wy < 7) ? 0 : ((ty < 4) ? 1 : 2);
        int wreg = (wx < 7) ? 0 : ((tx < 4) ? 1 : 2);
        sid[tid] = hreg * 3 + wreg;
    }
    __syncthreads();

    int r = tid;
    if (r < NTOK) {
        const float sc = 0.17677669529663687f;
        float4 q[8];
        const float* qp = g_qkv + base + (size_t)r * NQKV;
        #pragma unroll
        for (int dc = 0; dc < 8; dc++) {
            float4 v = *(const float4*)(qp + dc * 4);
            q[dc] = make_float4(v.x * sc, v.y * sc, v.z * sc, v.w * sc);
        }
        int iy = r / 7, ix = r - iy * 7;
        int myid = sid[r];
        float* srow = S + r * NTOK;
        float maxv = -1e30f;
        for (int mc = 0; mc < NTOK; mc++) {
            const float4* kp = &ksh[mc * 8];
            float dot = 0.f;
            #pragma unroll
            for (int dc = 0; dc < 8; dc++) {
                float4 kv = kp[dc];
                dot += q[dc].x * kv.x + q[dc].y * kv.y
                     + q[dc].z * kv.z + q[dc].w * kv.w;
            }
            int jy = mc / 7, jx = mc - jy * 7;
            float bval = table[((iy - jy + 6) * 13 + (ix - jx + 6)) * NHEADS + head];
            float val = dot + bval + ((sid[mc] != myid) ? -100.0f : 0.0f);
            srow[mc] = val;
            maxv = fmaxf(maxv, val);
        }
        float sum = 0.f;
        for (int mc = 0; mc < NTOK; mc++) {
            float e = __expf(srow[mc] - maxv);
            srow[mc] = e;
            sum += e;
        }
        float inv = 1.0f / sum;
        float o[32] = {};
        for (int mc = 0; mc < NTOK; mc++) {
            float p = srow[mc] * inv;
            const float4* vp = &vsh[mc * 8];
            #pragma unroll
            for (int dc = 0; dc < 8; dc++) {
                float4 vv = vp[dc];
                o[dc*4+0] += p * vv.x; o[dc*4+1] += p * vv.y;
                o[dc*4+2] += p * vv.z; o[dc*4+3] += p * vv.w;
            }
        }
        float* op = g_att + (size_t)(win * NTOK + r) * CDIM + head * HDIM;
        #pragma unroll
        for (int dc = 0; dc < 8; dc++)
            *(float4*)(op + dc * 4) =
                make_float4(o[dc*4], o[dc*4+1], o[dc*4+2], o[dc*4+3]);
    }
}

extern "C" void kernel_launch(void* const* d_in, const int* in_sizes, int n_in,
                              void* d_out, int out_size) {
    const float* x     = (const float*)d_in[0];
    const float* wqkv  = (const float*)d_in[1];
    const float* bqkv  = (const float*)d_in[2];
    const float* wproj = (const float*)d_in[3];
    const float* bproj = (const float*)d_in[4];
    const float* table = (const float*)d_in[5];
    float* out = (float*)d_out;

    float* qkv_ptr; cudaGetSymbolAddress((void**)&qkv_ptr, g_qkv);
    float* att_ptr; cudaGetSymbolAddress((void**)&att_ptr, g_att);

    gemm_mma_kernel<true, false><<<dim3(NQKV / TILE_MN, M_TOT / TILE_MN), 256>>>(
        x, wqkv, bqkv, qkv_ptr, CDIM, NQKV);
    attn_kernel<<<dim3(NHEADS, WIN_TOT), 64>>>(table);
    gemm_mma_kernel<false, true><<<dim3(CDIM / TILE_MN, M_TOT / TILE_MN), 256>>>(
        att_ptr, wproj, bproj, out, CDIM, CDIM);
}

// round 5
// speedup vs baseline: 4.2992x; 1.5254x over previous
#include <cuda_runtime.h>
#include <cuda_fp16.h>
#include <cstdint>

#define BATCH     16
#define IMG       56
#define CDIM      384
#define NHEADS    12
#define HDIM      32
#define NTOK      49
#define WIN_TOT   1024
#define M_TOT     50176
#define KDIM      384
#define NQKV      1152

#define TILE_MN   128
#define KC        64
#define NCHUNK    6
#define SMEM_GEMM 65536     // 2 stages x (16KB A + 16KB B)

// fp16 scratch (uint4 arrays for 16B alignment)
__device__ uint4 g_xh4   [(size_t)M_TOT * KDIM  / 8];   // gathered x, fp16 [m][384]
__device__ uint4 g_qkvh4 [(size_t)M_TOT * NQKV  / 8];   // qkv, fp16 [m][1152]
__device__ uint4 g_atth4 [(size_t)M_TOT * CDIM  / 8];   // attn out, fp16 [m][384]
__device__ uint4 g_wqkvh4[(size_t)NQKV  * KDIM  / 8];
__device__ uint4 g_wph4  [(size_t)CDIM  * KDIM  / 8];

__device__ __forceinline__ uint32_t smem_u32(const void* p) {
    uint32_t a;
    asm("{ .reg .u64 t; cvta.to.shared.u64 t, %1; cvt.u32.u64 %0, t; }"
        : "=r"(a) : "l"(p));
    return a;
}

// roll(-3,-3) + window-partition gather offset for row m = win*49 + tok
__device__ __forceinline__ int pix_offset(int m) {
    int win = m / 49;
    int tok = m - win * 49;
    int b  = win >> 6;
    int wi = win & 63;
    int wy = wi >> 3, wx = wi & 7;
    int ty = tok / 7, tx = tok - ty * 7;
    int h = wy * 7 + ty + 3; if (h >= IMG) h -= IMG;
    int w = wx * 7 + tx + 3; if (w >= IMG) w -= IMG;
    return ((b * IMG + h) * IMG + w) * CDIM;
}

#define CP_ASYNC16(dst, src) \
    asm volatile("cp.async.cg.shared.global [%0], [%1], 16;" :: "r"(dst), "l"(src))
#define CP_COMMIT() asm volatile("cp.async.commit_group;" ::: "memory")
template<int N> __device__ __forceinline__ void cp_wait() {
    asm volatile("cp.async.wait_group %0;" :: "n"(N) : "memory");
}

__device__ __forceinline__ void ldmatrix_x4(uint32_t addr, uint32_t& r0,
                                            uint32_t& r1, uint32_t& r2, uint32_t& r3) {
    asm volatile("ldmatrix.sync.aligned.m8n8.x4.shared.b16 {%0,%1,%2,%3}, [%4];"
                 : "=r"(r0), "=r"(r1), "=r"(r2), "=r"(r3) : "r"(addr));
}

__device__ __forceinline__ void mma16816(float* d, const uint32_t* a, const uint32_t* b) {
    asm volatile(
        "mma.sync.aligned.m16n8k16.row.col.f32.f16.f16.f32 "
        "{%0,%1,%2,%3}, {%4,%5,%6,%7}, {%8,%9}, {%0,%1,%2,%3};"
        : "+f"(d[0]), "+f"(d[1]), "+f"(d[2]), "+f"(d[3])
        : "r"(a[0]), "r"(a[1]), "r"(a[2]), "r"(a[3]), "r"(b[0]), "r"(b[1]));
}

// ---------------------------------------------------------------------------
// Converters
// ---------------------------------------------------------------------------
__global__ __launch_bounds__(256) void convert_gather_x(const float* __restrict__ x)
{
    __half* dst = (__half*)g_xh4;
    int i4 = blockIdx.x * 256 + threadIdx.x;           // 4 elems each
    int m  = i4 / 96, k4 = (i4 % 96) * 4;
    float4 v = *(const float4*)(x + pix_offset(m) + k4);
    __half2 h0 = __floats2half2_rn(v.x, v.y);
    __half2 h1 = __floats2half2_rn(v.z, v.w);
    *(uint2*)(dst + (size_t)m * KDIM + k4) =
        make_uint2(*(uint32_t*)&h0, *(uint32_t*)&h1);
}

__global__ __launch_bounds__(256) void convert_lin(const float* __restrict__ s,
                                                   __half* __restrict__ d)
{
    int i4 = (blockIdx.x * 256 + threadIdx.x) * 4;
    float4 v = *(const float4*)(s + i4);
    __half2 h0 = __floats2half2_rn(v.x, v.y);
    __half2 h1 = __floats2half2_rn(v.z, v.w);
    *(uint2*)(d + i4) = make_uint2(*(uint32_t*)&h0, *(uint32_t*)&h1);
}

// ---------------------------------------------------------------------------
// fp16 GEMM, cp.async double-buffered. Out = A . W^T + bias
// OUTMODE 0: fp16 linear store (ldOut).  OUTMODE 1: fp32 scatter via pix_offset.
// ---------------------------------------------------------------------------
template<int OUTMODE>
__global__ __launch_bounds__(256) void gemm16_kernel(
    const __half* __restrict__ A, const __half* __restrict__ W,
    const float* __restrict__ bias, void* __restrict__ Out, int ldOut)
{
    extern __shared__ __align__(128) char smem[];
    uint32_t sb = smem_u32(smem);

    int tid  = threadIdx.x;
    int lane = tid & 31, wid = tid >> 5;
    int warpM = wid >> 2, warpN = wid & 3;
    int tileM0 = blockIdx.y * TILE_MN;
    int n0 = blockIdx.x * TILE_MN;

    float acc[4][4][4] = {};

    int rowA = warpM * 64 + (lane & 15);
    int kA   = (lane >> 4) * 8;
    uint32_t xa = (uint32_t)((rowA & 7) << 4);
    int rowB = warpN * 32 + (lane & 7) + ((lane >> 4) << 3);
    int kB   = ((lane >> 3) & 1) * 8;
    uint32_t xb = (uint32_t)((rowB & 7) << 4);

    // loader geometry: 1024 x 16B per tile; 4 slots/thread
    int lr = tid >> 3;       // row base, +32 per iter
    int lc = tid & 7;        // 16B chunk in 128B row

    const __half* Arow = A + (size_t)tileM0 * KDIM;
    const __half* Wrow = W + (size_t)n0 * KDIM;

    auto load_chunk = [&](int c) {
        uint32_t stage = sb + (uint32_t)((c & 1) * 32768);
        #pragma unroll
        for (int it = 0; it < 4; ++it) {
            int r = lr + it * 32;
            uint32_t off = ((uint32_t)(r * 128 + lc * 16)) ^ ((uint32_t)((r & 7) << 4));
            CP_ASYNC16(stage + off,          Arow + (size_t)r * KDIM + c * KC + lc * 8);
            CP_ASYNC16(stage + 16384 + off,  Wrow + (size_t)r * KDIM + c * KC + lc * 8);
        }
        CP_COMMIT();
    };

    load_chunk(0);

    for (int c = 0; c < NCHUNK; ++c) {
        if (c + 1 < NCHUNK) { load_chunk(c + 1); cp_wait<1>(); }
        else                { cp_wait<0>(); }
        __syncthreads();

        uint32_t sA = sb + (uint32_t)((c & 1) * 32768);
        uint32_t sB = sA + 16384;
        #pragma unroll
        for (int ks = 0; ks < 4; ++ks) {
            uint32_t a[4][4], b[4][2];
            #pragma unroll
            for (int mt = 0; mt < 4; ++mt) {
                uint32_t addr = sA + ((uint32_t)((rowA + mt * 16) * 128 + ks * 32 + kA * 2) ^ xa);
                ldmatrix_x4(addr, a[mt][0], a[mt][1], a[mt][2], a[mt][3]);
            }
            #pragma unroll
            for (int p = 0; p < 2; ++p) {
                uint32_t addr = sB + ((uint32_t)((rowB + p * 16) * 128 + ks * 32 + kB * 2) ^ xb);
                uint32_t r0, r1, r2, r3;
                ldmatrix_x4(addr, r0, r1, r2, r3);
                b[2 * p][0] = r0;     b[2 * p][1] = r1;
                b[2 * p + 1][0] = r2; b[2 * p + 1][1] = r3;
            }
            #pragma unroll
            for (int mt = 0; mt < 4; ++mt)
                #pragma unroll
                for (int nt = 0; nt < 4; ++nt)
                    mma16816(acc[mt][nt], a[mt], b[nt]);
        }
        __syncthreads();
    }

    #pragma unroll
    for (int mt = 0; mt < 4; ++mt) {
        int m = tileM0 + warpM * 64 + mt * 16 + (lane >> 2);
        #pragma unroll
        for (int nt = 0; nt < 4; ++nt) {
            int n = n0 + warpN * 32 + nt * 8 + (lane & 3) * 2;
            float bx = __ldg(bias + n), by = __ldg(bias + n + 1);
            if (OUTMODE == 0) {
                __half* o = (__half*)Out;
                __half2 h0 = __floats2half2_rn(acc[mt][nt][0] + bx, acc[mt][nt][1] + by);
                __half2 h1 = __floats2half2_rn(acc[mt][nt][2] + bx, acc[mt][nt][3] + by);
                *(__half2*)(o + (size_t)m * ldOut + n) = h0;
                *(__half2*)(o + (size_t)(m + 8) * ldOut + n) = h1;
            } else {
                float* o = (float*)Out;
                *(float2*)(o + pix_offset(m) + n) =
                    make_float2(acc[mt][nt][0] + bx, acc[mt][nt][1] + by);
                *(float2*)(o + pix_offset(m + 8) + n) =
                    make_float2(acc[mt][nt][2] + bx, acc[mt][nt][3] + by);
            }
        }
    }
}

// ---------------------------------------------------------------------------
// Attention: block per (head, window). fp16 in/out, fp32 math, bias in smem.
// ---------------------------------------------------------------------------
__global__ __launch_bounds__(64) void attn_kernel(const float* __restrict__ table)
{
    __shared__ __align__(16) float ksh[NTOK * HDIM];
    __shared__ __align__(16) float vsh[NTOK * HDIM];
    __shared__ float  S[NTOK * NTOK];
    __shared__ float  bias_s[169];
    __shared__ int    sid[NTOK];

    int head = blockIdx.x;
    int win  = blockIdx.y;
    int tid  = threadIdx.x;

    const __half* qkvh = (const __half*)g_qkvh4;
    size_t base = (size_t)win * NTOK * NQKV + head * HDIM;

    for (int f = tid; f < NTOK * 16; f += 64) {
        int t = f >> 4, dc = f & 15;
        size_t off = base + (size_t)t * NQKV + dc * 2;
        float2 kv = __half22float2(*(const __half2*)(qkvh + off + 384));
        float2 vv = __half22float2(*(const __half2*)(qkvh + off + 768));
        *(float2*)&ksh[t * HDIM + dc * 2] = kv;
        *(float2*)&vsh[t * HDIM + dc * 2] = vv;
    }
    for (int i = tid; i < 169; i += 64)
        bias_s[i] = table[i * NHEADS + head];
    if (tid < NTOK) {
        int wy = (win & 63) >> 3, wx = win & 7;
        int ty = tid / 7, tx = tid - ty * 7;
        int hreg = (wy < 7) ? 0 : ((ty < 4) ? 1 : 2);
        int wreg = (wx < 7) ? 0 : ((tx < 4) ? 1 : 2);
        sid[tid] = hreg * 3 + wreg;
    }
    __syncthreads();

    int r = tid;
    if (r < NTOK) {
        const float sc = 0.17677669529663687f;
        float4 q[8];
        const __half* qp = qkvh + base + (size_t)r * NQKV;
        #pragma unroll
        for (int dc = 0; dc < 8; dc++) {
            float2 a = __half22float2(*(const __half2*)(qp + dc * 4));
            float2 b = __half22float2(*(const __half2*)(qp + dc * 4 + 2));
            q[dc] = make_float4(a.x * sc, a.y * sc, b.x * sc, b.y * sc);
        }
        int iy = r / 7, ix = r - iy * 7;
        int myid = sid[r];
        float* srow = S + r * NTOK;
        float maxv = -1e30f;
        for (int mc = 0; mc < NTOK; mc++) {
            const float4* kp = (const float4*)&ksh[mc * HDIM];
            float dot = 0.f;
            #pragma unroll
            for (int dc = 0; dc < 8; dc++) {
                float4 kv = kp[dc];
                dot += q[dc].x * kv.x + q[dc].y * kv.y
                     + q[dc].z * kv.z + q[dc].w * kv.w;
            }
            int jy = mc / 7, jx = mc - jy * 7;
            float val = dot + bias_s[(iy - jy + 6) * 13 + (ix - jx + 6)]
                            + ((sid[mc] != myid) ? -100.0f : 0.0f);
            srow[mc] = val;
            maxv = fmaxf(maxv, val);
        }
        float sum = 0.f;
        for (int mc = 0; mc < NTOK; mc++) {
            float e = __expf(srow[mc] - maxv);
            srow[mc] = e;
            sum += e;
        }
        float inv = 1.0f / sum;
        float o[32] = {};
        for (int mc = 0; mc < NTOK; mc++) {
            float p = srow[mc] * inv;
            const float4* vp = (const float4*)&vsh[mc * HDIM];
            #pragma unroll
            for (int dc = 0; dc < 8; dc++) {
                float4 vv = vp[dc];
                o[dc*4+0] += p * vv.x; o[dc*4+1] += p * vv.y;
                o[dc*4+2] += p * vv.z; o[dc*4+3] += p * vv.w;
            }
        }
        __half* op = (__half*)g_atth4 + (size_t)(win * NTOK + r) * CDIM + head * HDIM;
        #pragma unroll
        for (int dc = 0; dc < 16; dc++)
            *(__half2*)(op + dc * 2) = __floats2half2_rn(o[dc*2], o[dc*2+1]);
    }
}

extern "C" void kernel_launch(void* const* d_in, const int* in_sizes, int n_in,
                              void* d_out, int out_size) {
    const float* x     = (const float*)d_in[0];
    const float* wqkv  = (const float*)d_in[1];
    const float* bqkv  = (const float*)d_in[2];
    const float* wproj = (const float*)d_in[3];
    const float* bproj = (const float*)d_in[4];
    const float* table = (const float*)d_in[5];
    float* out = (float*)d_out;

    __half *xh, *qkvh, *atth, *wqkvh, *wph;
    cudaGetSymbolAddress((void**)&xh,    g_xh4);
    cudaGetSymbolAddress((void**)&qkvh,  g_qkvh4);
    cudaGetSymbolAddress((void**)&atth,  g_atth4);
    cudaGetSymbolAddress((void**)&wqkvh, g_wqkvh4);
    cudaGetSymbolAddress((void**)&wph,   g_wph4);

    cudaFuncSetAttribute(gemm16_kernel<0>,
                         cudaFuncAttributeMaxDynamicSharedMemorySize, SMEM_GEMM);
    cudaFuncSetAttribute(gemm16_kernel<1>,
                         cudaFuncAttributeMaxDynamicSharedMemorySize, SMEM_GEMM);

    convert_gather_x<<<M_TOT * KDIM / 4 / 256, 256>>>(x);
    convert_lin<<<NQKV * KDIM / 4 / 256, 256>>>(wqkv, wqkvh);
    convert_lin<<<CDIM * KDIM / 4 / 256, 256>>>(wproj, wph);

    gemm16_kernel<0><<<dim3(NQKV / TILE_MN, M_TOT / TILE_MN), 256, SMEM_GEMM>>>(
        xh, wqkvh, bqkv, qkvh, NQKV);
    attn_kernel<<<dim3(NHEADS, WIN_TOT), 64>>>(table);
    gemm16_kernel<1><<<dim3(CDIM / TILE_MN, M_TOT / TILE_MN), 256, SMEM_GEMM>>>(
        atth, wph, bproj, out, 0);
}

// round 6
// speedup vs baseline: 4.4399x; 1.0327x over previous
#include <cuda_runtime.h>
#include <cuda_fp16.h>
#include <cstdint>

#define BATCH     16
#define IMG       56
#define CDIM      384
#define NHEADS    12
#define HDIM      32
#define NTOK      49
#define WIN_TOT   1024
#define M_TOT     50176
#define KDIM      384
#define NQKV      1152

#define TILE_MN   128
#define KC        64
#define NCHUNK    6
#define SMEM_GEMM 65536

// fp16 scratch
__device__ uint4 g_xh4   [(size_t)M_TOT * KDIM  / 8];
__device__ uint4 g_qkvh4 [(size_t)M_TOT * NQKV  / 8];
__device__ uint4 g_atth4 [(size_t)M_TOT * CDIM  / 8];
__device__ uint4 g_wqkvh4[(size_t)NQKV  * KDIM  / 8];
__device__ uint4 g_wph4  [(size_t)CDIM  * KDIM  / 8];

__device__ __forceinline__ uint32_t smem_u32(const void* p) {
    uint32_t a;
    asm("{ .reg .u64 t; cvta.to.shared.u64 t, %1; cvt.u32.u64 %0, t; }"
        : "=r"(a) : "l"(p));
    return a;
}

__device__ __forceinline__ int pix_offset(int m) {
    int win = m / 49;
    int tok = m - win * 49;
    int b  = win >> 6;
    int wi = win & 63;
    int wy = wi >> 3, wx = wi & 7;
    int ty = tok / 7, tx = tok - ty * 7;
    int h = wy * 7 + ty + 3; if (h >= IMG) h -= IMG;
    int w = wx * 7 + tx + 3; if (w >= IMG) w -= IMG;
    return ((b * IMG + h) * IMG + w) * CDIM;
}

#define CP_ASYNC16(dst, src) \
    asm volatile("cp.async.cg.shared.global [%0], [%1], 16;" :: "r"(dst), "l"(src))
#define CP_COMMIT() asm volatile("cp.async.commit_group;" ::: "memory")
template<int N> __device__ __forceinline__ void cp_wait() {
    asm volatile("cp.async.wait_group %0;" :: "n"(N) : "memory");
}

__device__ __forceinline__ void ldmatrix_x4(uint32_t addr, uint32_t& r0,
                                            uint32_t& r1, uint32_t& r2, uint32_t& r3) {
    asm volatile("ldmatrix.sync.aligned.m8n8.x4.shared.b16 {%0,%1,%2,%3}, [%4];"
                 : "=r"(r0), "=r"(r1), "=r"(r2), "=r"(r3) : "r"(addr));
}

__device__ __forceinline__ void mma16816(float* d, const uint32_t* a, const uint32_t* b) {
    asm volatile(
        "mma.sync.aligned.m16n8k16.row.col.f32.f16.f16.f32 "
        "{%0,%1,%2,%3}, {%4,%5,%6,%7}, {%8,%9}, {%0,%1,%2,%3};"
        : "+f"(d[0]), "+f"(d[1]), "+f"(d[2]), "+f"(d[3])
        : "r"(a[0]), "r"(a[1]), "r"(a[2]), "r"(a[3]), "r"(b[0]), "r"(b[1]));
}

__device__ __forceinline__ uint32_t packh2(float x, float y) {
    __half2 h = __floats2half2_rn(x, y);
    return *(uint32_t*)&h;
}

// ---------------------------------------------------------------------------
// Converters
// ---------------------------------------------------------------------------
__global__ __launch_bounds__(256) void convert_gather_x(const float* __restrict__ x)
{
    __half* dst = (__half*)g_xh4;
    int i4 = blockIdx.x * 256 + threadIdx.x;
    int m  = i4 / 96, k4 = (i4 % 96) * 4;
    float4 v = *(const float4*)(x + pix_offset(m) + k4);
    __half2 h0 = __floats2half2_rn(v.x, v.y);
    __half2 h1 = __floats2half2_rn(v.z, v.w);
    *(uint2*)(dst + (size_t)m * KDIM + k4) =
        make_uint2(*(uint32_t*)&h0, *(uint32_t*)&h1);
}

__global__ __launch_bounds__(256) void convert_lin(const float* __restrict__ s,
                                                   __half* __restrict__ d)
{
    int i4 = (blockIdx.x * 256 + threadIdx.x) * 4;
    float4 v = *(const float4*)(s + i4);
    __half2 h0 = __floats2half2_rn(v.x, v.y);
    __half2 h1 = __floats2half2_rn(v.z, v.w);
    *(uint2*)(d + i4) = make_uint2(*(uint32_t*)&h0, *(uint32_t*)&h1);
}

// ---------------------------------------------------------------------------
// fp16 GEMM, cp.async double-buffered (unchanged from R5 — proven)
// ---------------------------------------------------------------------------
template<int OUTMODE>
__global__ __launch_bounds__(256) void gemm16_kernel(
    const __half* __restrict__ A, const __half* __restrict__ W,
    const float* __restrict__ bias, void* __restrict__ Out, int ldOut)
{
    extern __shared__ __align__(128) char smem[];
    uint32_t sb = smem_u32(smem);

    int tid  = threadIdx.x;
    int lane = tid & 31, wid = tid >> 5;
    int warpM = wid >> 2, warpN = wid & 3;
    int tileM0 = blockIdx.y * TILE_MN;
    int n0 = blockIdx.x * TILE_MN;

    float acc[4][4][4] = {};

    int rowA = warpM * 64 + (lane & 15);
    int kA   = (lane >> 4) * 8;
    uint32_t xa = (uint32_t)((rowA & 7) << 4);
    int rowB = warpN * 32 + (lane & 7) + ((lane >> 4) << 3);
    int kB   = ((lane >> 3) & 1) * 8;
    uint32_t xb = (uint32_t)((rowB & 7) << 4);

    int lr = tid >> 3;
    int lc = tid & 7;

    const __half* Arow = A + (size_t)tileM0 * KDIM;
    const __half* Wrow = W + (size_t)n0 * KDIM;

    auto load_chunk = [&](int c) {
        uint32_t stage = sb + (uint32_t)((c & 1) * 32768);
        #pragma unroll
        for (int it = 0; it < 4; ++it) {
            int r = lr + it * 32;
            uint32_t off = ((uint32_t)(r * 128 + lc * 16)) ^ ((uint32_t)((r & 7) << 4));
            CP_ASYNC16(stage + off,          Arow + (size_t)r * KDIM + c * KC + lc * 8);
            CP_ASYNC16(stage + 16384 + off,  Wrow + (size_t)r * KDIM + c * KC + lc * 8);
        }
        CP_COMMIT();
    };

    load_chunk(0);

    for (int c = 0; c < NCHUNK; ++c) {
        if (c + 1 < NCHUNK) { load_chunk(c + 1); cp_wait<1>(); }
        else                { cp_wait<0>(); }
        __syncthreads();

        uint32_t sA = sb + (uint32_t)((c & 1) * 32768);
        uint32_t sB = sA + 16384;
        #pragma unroll
        for (int ks = 0; ks < 4; ++ks) {
            uint32_t a[4][4], b[4][2];
            #pragma unroll
            for (int mt = 0; mt < 4; ++mt) {
                uint32_t addr = sA + ((uint32_t)((rowA + mt * 16) * 128 + ks * 32 + kA * 2) ^ xa);
                ldmatrix_x4(addr, a[mt][0], a[mt][1], a[mt][2], a[mt][3]);
            }
            #pragma unroll
            for (int p = 0; p < 2; ++p) {
                uint32_t addr = sB + ((uint32_t)((rowB + p * 16) * 128 + ks * 32 + kB * 2) ^ xb);
                uint32_t r0, r1, r2, r3;
                ldmatrix_x4(addr, r0, r1, r2, r3);
                b[2 * p][0] = r0;     b[2 * p][1] = r1;
                b[2 * p + 1][0] = r2; b[2 * p + 1][1] = r3;
            }
            #pragma unroll
            for (int mt = 0; mt < 4; ++mt)
                #pragma unroll
                for (int nt = 0; nt < 4; ++nt)
                    mma16816(acc[mt][nt], a[mt], b[nt]);
        }
        __syncthreads();
    }

    #pragma unroll
    for (int mt = 0; mt < 4; ++mt) {
        int m = tileM0 + warpM * 64 + mt * 16 + (lane >> 2);
        #pragma unroll
        for (int nt = 0; nt < 4; ++nt) {
            int n = n0 + warpN * 32 + nt * 8 + (lane & 3) * 2;
            float bx = __ldg(bias + n), by = __ldg(bias + n + 1);
            if (OUTMODE == 0) {
                __half* o = (__half*)Out;
                __half2 h0 = __floats2half2_rn(acc[mt][nt][0] + bx, acc[mt][nt][1] + by);
                __half2 h1 = __floats2half2_rn(acc[mt][nt][2] + bx, acc[mt][nt][3] + by);
                *(__half2*)(o + (size_t)m * ldOut + n) = h0;
                *(__half2*)(o + (size_t)(m + 8) * ldOut + n) = h1;
            } else {
                float* o = (float*)Out;
                *(float2*)(o + pix_offset(m) + n) =
                    make_float2(acc[mt][nt][0] + bx, acc[mt][nt][1] + by);
                *(float2*)(o + pix_offset(m + 8) + n) =
                    make_float2(acc[mt][nt][2] + bx, acc[mt][nt][3] + by);
            }
        }
    }
}

// ---------------------------------------------------------------------------
// Tensor-core attention. Block = (head, window), 128 threads (4 warps).
// Warp w owns row tile [16w, 16w+16). S = Q K^T via mma (N padded to 56),
// softmax on register fragments, P kept as fp16 a-fragments, O = P V via mma
// with V transposed in smem. 1/sum applied in fp32 on O.
// ---------------------------------------------------------------------------
#define QK_STRIDE 40     // halves per row (80B: conflict-free 5i mod 8)
#define VT_STRIDE 72     // halves per row (144B: conflict-free 9i mod 8)

__global__ __launch_bounds__(128) void attn_mma_kernel(const float* __restrict__ table)
{
    __shared__ __align__(16) __half Qs[64 * QK_STRIDE];
    __shared__ __align__(16) __half Ks[64 * QK_STRIDE];
    __shared__ __align__(16) __half Vt[32 * VT_STRIDE];
    __shared__ float bias_s[169];
    __shared__ int   sid_s[49];

    int head = blockIdx.x;
    int win  = blockIdx.y;
    int tid  = threadIdx.x;
    int lane = tid & 31, wid = tid >> 5;

    const __half* qkvh = (const __half*)g_qkvh4;
    size_t base = (size_t)win * NTOK * NQKV + head * HDIM;

    // ---- load: Q (scaled), K, V^T; 256 slots = 64 rows x 4 chunks of 8 halves
    const __half2 sc2 = __floats2half2_rn(0.17677669529663687f, 0.17677669529663687f);
    for (int f = tid; f < 256; f += 128) {
        int r = f >> 2, c = f & 3;
        uint4 qv = make_uint4(0, 0, 0, 0), kv = qv, vv = qv;
        if (r < NTOK) {
            const __half* p = qkvh + base + (size_t)r * NQKV + c * 8;
            qv = *(const uint4*)p;
            kv = *(const uint4*)(p + 384);
            vv = *(const uint4*)(p + 768);
            __half2* qh = (__half2*)&qv;
            #pragma unroll
            for (int t = 0; t < 4; ++t) qh[t] = __hmul2(qh[t], sc2);
        }
        *(uint4*)&Qs[r * QK_STRIDE + c * 8] = qv;
        *(uint4*)&Ks[r * QK_STRIDE + c * 8] = kv;
        const __half* vh = (const __half*)&vv;
        #pragma unroll
        for (int d = 0; d < 8; ++d)
            Vt[(c * 8 + d) * VT_STRIDE + r] = vh[d];
    }
    for (int i = tid; i < 169; i += 128)
        bias_s[i] = table[i * NHEADS + head];
    if (tid < NTOK) {
        int wy = (win & 63) >> 3, wx = win & 7;
        int ty = tid / 7, tx = tid - ty * 7;
        int hreg = (wy < 7) ? 0 : ((ty < 4) ? 1 : 2);
        int wreg = (wx < 7) ? 0 : ((tx < 4) ? 1 : 2);
        sid_s[tid] = hreg * 3 + wreg;
    }
    __syncthreads();

    uint32_t sQ = smem_u32(Qs), sK = smem_u32(Ks), sV = smem_u32(Vt);

    int gid = lane >> 2, tig = lane & 3;
    int rowbase = wid * 16;

    // ---- S = Q K^T : 7 n8 tiles x 2 k16 steps
    float s[7][4] = {};
    int aRow = rowbase + (lane & 15);
    int aK   = (lane >> 4) * 8;
    int bRow = (lane & 7) + ((lane >> 4) << 3);
    int bK   = ((lane >> 3) & 1) * 8;
    #pragma unroll
    for (int ks = 0; ks < 2; ++ks) {
        uint32_t a[4];
        ldmatrix_x4(sQ + (uint32_t)(aRow * QK_STRIDE + ks * 16 + aK) * 2,
                    a[0], a[1], a[2], a[3]);
        #pragma unroll
        for (int p = 0; p < 4; ++p) {
            uint32_t r0, r1, r2, r3;
            ldmatrix_x4(sK + (uint32_t)((p * 16 + bRow) * QK_STRIDE + ks * 16 + bK) * 2,
                        r0, r1, r2, r3);
            uint32_t b0[2] = {r0, r1}, b1[2] = {r2, r3};
            mma16816(s[2 * p], a, b0);
            if (p < 3) mma16816(s[2 * p + 1], a, b1);
        }
    }

    // ---- bias + mask + softmax on fragments
    int r0 = rowbase + gid, r1 = r0 + 8;
    int i0 = (r0 < NTOK) ? r0 : 48;
    int i1 = (r1 < NTOK) ? r1 : 48;
    int iy0 = i0 / 7, ix0 = i0 - iy0 * 7, sd0 = sid_s[i0];
    int iy1 = i1 / 7, ix1 = i1 - iy1 * 7, sd1 = sid_s[i1];

    #pragma unroll
    for (int n = 0; n < 7; ++n) {
        #pragma unroll
        for (int e = 0; e < 2; ++e) {
            int j = n * 8 + tig * 2 + e;
            if (j < NTOK) {
                int jy = j / 7, jx = j - jy * 7;
                int sdj = sid_s[j];
                float b0 = bias_s[(iy0 - jy + 6) * 13 + (ix0 - jx + 6)];
                float b1 = bias_s[(iy1 - jy + 6) * 13 + (ix1 - jx + 6)];
                s[n][e]     += b0 + ((sdj != sd0) ? -100.f : 0.f);
                s[n][2 + e] += b1 + ((sdj != sd1) ? -100.f : 0.f);
            } else {
                s[n][e] = -1e9f;
                s[n][2 + e] = -1e9f;
            }
        }
    }

    float mx0 = -1e30f, mx1 = -1e30f;
    #pragma unroll
    for (int n = 0; n < 7; ++n) {
        mx0 = fmaxf(mx0, fmaxf(s[n][0], s[n][1]));
        mx1 = fmaxf(mx1, fmaxf(s[n][2], s[n][3]));
    }
    mx0 = fmaxf(mx0, __shfl_xor_sync(0xffffffffu, mx0, 1));
    mx0 = fmaxf(mx0, __shfl_xor_sync(0xffffffffu, mx0, 2));
    mx1 = fmaxf(mx1, __shfl_xor_sync(0xffffffffu, mx1, 1));
    mx1 = fmaxf(mx1, __shfl_xor_sync(0xffffffffu, mx1, 2));

    float sm0 = 0.f, sm1 = 0.f;
    #pragma unroll
    for (int n = 0; n < 7; ++n) {
        s[n][0] = __expf(s[n][0] - mx0); sm0 += s[n][0];
        s[n][1] = __expf(s[n][1] - mx0); sm0 += s[n][1];
        s[n][2] = __expf(s[n][2] - mx1); sm1 += s[n][2];
        s[n][3] = __expf(s[n][3] - mx1); sm1 += s[n][3];
    }
    sm0 += __shfl_xor_sync(0xffffffffu, sm0, 1);
    sm0 += __shfl_xor_sync(0xffffffffu, sm0, 2);
    sm1 += __shfl_xor_sync(0xffffffffu, sm1, 1);
    sm1 += __shfl_xor_sync(0xffffffffu, sm1, 2);
    float inv0 = 1.0f / sm0, inv1 = 1.0f / sm1;

    // ---- P fragments (fp16, unnormalized)
    uint32_t aP[4][4];
    #pragma unroll
    for (int kt = 0; kt < 4; ++kt) {
        aP[kt][0] = packh2(s[2 * kt][0], s[2 * kt][1]);
        aP[kt][1] = packh2(s[2 * kt][2], s[2 * kt][3]);
        if (kt < 3) {
            aP[kt][2] = packh2(s[2 * kt + 1][0], s[2 * kt + 1][1]);
            aP[kt][3] = packh2(s[2 * kt + 1][2], s[2 * kt + 1][3]);
        } else {
            aP[kt][2] = 0; aP[kt][3] = 0;
        }
    }

    // ---- O = P V : N=32 (4 n8), K=64 (4 k16)
    float o[4][4] = {};
    #pragma unroll
    for (int kt = 0; kt < 4; ++kt) {
        #pragma unroll
        for (int np = 0; np < 2; ++np) {
            uint32_t r0v, r1v, r2v, r3v;
            ldmatrix_x4(sV + (uint32_t)((np * 16 + bRow) * VT_STRIDE + kt * 16 + bK) * 2,
                        r0v, r1v, r2v, r3v);
            uint32_t b0[2] = {r0v, r1v}, b1[2] = {r2v, r3v};
            mma16816(o[2 * np], aP[kt], b0);
            mma16816(o[2 * np + 1], aP[kt], b1);
        }
    }

    // ---- store O (fp16) with fp32 normalization
    __half* att = (__half*)g_atth4;
    #pragma unroll
    for (int nt = 0; nt < 4; ++nt) {
        int col = head * HDIM + nt * 8 + tig * 2;
        if (r0 < NTOK)
            *(__half2*)(att + (size_t)(win * NTOK + r0) * CDIM + col) =
                __floats2half2_rn(o[nt][0] * inv0, o[nt][1] * inv0);
        if (r1 < NTOK)
            *(__half2*)(att + (size_t)(win * NTOK + r1) * CDIM + col) =
                __floats2half2_rn(o[nt][2] * inv1, o[nt][3] * inv1);
    }
}

extern "C" void kernel_launch(void* const* d_in, const int* in_sizes, int n_in,
                              void* d_out, int out_size) {
    const float* x     = (const float*)d_in[0];
    const float* wqkv  = (const float*)d_in[1];
    const float* bqkv  = (const float*)d_in[2];
    const float* wproj = (const float*)d_in[3];
    const float* bproj = (const float*)d_in[4];
    const float* table = (const float*)d_in[5];
    float* out = (float*)d_out;

    __half *xh, *qkvh, *atth, *wqkvh, *wph;
    cudaGetSymbolAddress((void**)&xh,    g_xh4);
    cudaGetSymbolAddress((void**)&qkvh,  g_qkvh4);
    cudaGetSymbolAddress((void**)&atth,  g_atth4);
    cudaGetSymbolAddress((void**)&wqkvh, g_wqkvh4);
    cudaGetSymbolAddress((void**)&wph,   g_wph4);

    cudaFuncSetAttribute(gemm16_kernel<0>,
                         cudaFuncAttributeMaxDynamicSharedMemorySize, SMEM_GEMM);
    cudaFuncSetAttribute(gemm16_kernel<1>,
                         cudaFuncAttributeMaxDynamicSharedMemorySize, SMEM_GEMM);

    convert_gather_x<<<M_TOT * KDIM / 4 / 256, 256>>>(x);
    convert_lin<<<NQKV * KDIM / 4 / 256, 256>>>(wqkv, wqkvh);
    convert_lin<<<CDIM * KDIM / 4 / 256, 256>>>(wproj, wph);

    gemm16_kernel<0><<<dim3(NQKV / TILE_MN, M_TOT / TILE_MN), 256, SMEM_GEMM>>>(
        xh, wqkvh, bqkv, qkvh, NQKV);
    attn_mma_kernel<<<dim3(NHEADS, WIN_TOT), 128>>>(table);
    gemm16_kernel<1><<<dim3(CDIM / TILE_MN, M_TOT / TILE_MN), 256, SMEM_GEMM>>>(
        atth, wph, bproj, out, 0);
}

// round 7
// speedup vs baseline: 5.8527x; 1.3182x over previous
#include <cuda_runtime.h>
#include <cuda_fp16.h>
#include <cstdint>

#define BATCH     16
#define IMG       56
#define CDIM      384
#define NHEADS    12
#define HDIM      32
#define NTOK      49
#define WIN_TOT   1024
#define M_TOT     50176
#define KDIM      384
#define NQKV      1152

#define TILE_MN   128
#define KC        64
#define NCHUNK    6
#define STAGE_BYTES 32768
#define SMEM_GEMM (3 * STAGE_BYTES)      // 3-stage pipeline

// fp16 scratch
__device__ uint4 g_xh4   [(size_t)M_TOT * KDIM  / 8];
__device__ uint4 g_qkvh4 [(size_t)M_TOT * NQKV  / 8];
__device__ uint4 g_atth4 [(size_t)M_TOT * CDIM  / 8];
__device__ uint4 g_wqkvh4[(size_t)NQKV  * KDIM  / 8];
__device__ uint4 g_wph4  [(size_t)CDIM  * KDIM  / 8];

__device__ __forceinline__ uint32_t smem_u32(const void* p) {
    uint32_t a;
    asm("{ .reg .u64 t; cvta.to.shared.u64 t, %1; cvt.u32.u64 %0, t; }"
        : "=r"(a) : "l"(p));
    return a;
}

__device__ __forceinline__ int pix_offset(int m) {
    int win = m / 49;
    int tok = m - win * 49;
    int b  = win >> 6;
    int wi = win & 63;
    int wy = wi >> 3, wx = wi & 7;
    int ty = tok / 7, tx = tok - ty * 7;
    int h = wy * 7 + ty + 3; if (h >= IMG) h -= IMG;
    int w = wx * 7 + tx + 3; if (w >= IMG) w -= IMG;
    return ((b * IMG + h) * IMG + w) * CDIM;
}

#define CP_ASYNC16(dst, src) \
    asm volatile("cp.async.cg.shared.global [%0], [%1], 16;" :: "r"(dst), "l"(src))
#define CP_COMMIT() asm volatile("cp.async.commit_group;" ::: "memory")
template<int N> __device__ __forceinline__ void cp_wait() {
    asm volatile("cp.async.wait_group %0;" :: "n"(N) : "memory");
}

__device__ __forceinline__ void ldmatrix_x4(uint32_t addr, uint32_t& r0,
                                            uint32_t& r1, uint32_t& r2, uint32_t& r3) {
    asm volatile("ldmatrix.sync.aligned.m8n8.x4.shared.b16 {%0,%1,%2,%3}, [%4];"
                 : "=r"(r0), "=r"(r1), "=r"(r2), "=r"(r3) : "r"(addr));
}

__device__ __forceinline__ void mma16816(float* d, const uint32_t* a, const uint32_t* b) {
    asm volatile(
        "mma.sync.aligned.m16n8k16.row.col.f32.f16.f16.f32 "
        "{%0,%1,%2,%3}, {%4,%5,%6,%7}, {%8,%9}, {%0,%1,%2,%3};"
        : "+f"(d[0]), "+f"(d[1]), "+f"(d[2]), "+f"(d[3])
        : "r"(a[0]), "r"(a[1]), "r"(a[2]), "r"(a[3]), "r"(b[0]), "r"(b[1]));
}

__device__ __forceinline__ uint32_t packh2(float x, float y) {
    __half2 h = __floats2half2_rn(x, y);
    return *(uint32_t*)&h;
}

// ---------------------------------------------------------------------------
// Converters
// ---------------------------------------------------------------------------
__global__ __launch_bounds__(256) void convert_gather_x(const float* __restrict__ x)
{
    __half* dst = (__half*)g_xh4;
    int i4 = blockIdx.x * 256 + threadIdx.x;
    int m  = i4 / 96, k4 = (i4 % 96) * 4;
    float4 v = *(const float4*)(x + pix_offset(m) + k4);
    __half2 h0 = __floats2half2_rn(v.x, v.y);
    __half2 h1 = __floats2half2_rn(v.z, v.w);
    *(uint2*)(dst + (size_t)m * KDIM + k4) =
        make_uint2(*(uint32_t*)&h0, *(uint32_t*)&h1);
}

// both weight matrices in one launch
__global__ __launch_bounds__(256) void convert_weights(
    const float* __restrict__ wqkv, const float* __restrict__ wproj)
{
    int i4 = (blockIdx.x * 256 + threadIdx.x) * 4;
    const float* s;
    __half* d;
    if (i4 < NQKV * KDIM) {
        s = wqkv + i4;
        d = (__half*)g_wqkvh4 + i4;
    } else {
        s = wproj + (i4 - NQKV * KDIM);
        d = (__half*)g_wph4 + (i4 - NQKV * KDIM);
    }
    float4 v = *(const float4*)s;
    __half2 h0 = __floats2half2_rn(v.x, v.y);
    __half2 h1 = __floats2half2_rn(v.z, v.w);
    *(uint2*)d = make_uint2(*(uint32_t*)&h0, *(uint32_t*)&h1);
}

// ---------------------------------------------------------------------------
// fp16 GEMM, cp.async 3-stage pipeline, ONE barrier per chunk.
// ---------------------------------------------------------------------------
template<int OUTMODE>
__global__ __launch_bounds__(256) void gemm16_kernel(
    const __half* __restrict__ A, const __half* __restrict__ W,
    const float* __restrict__ bias, void* __restrict__ Out, int ldOut)
{
    extern __shared__ __align__(128) char smem[];
    uint32_t sb = smem_u32(smem);

    int tid  = threadIdx.x;
    int lane = tid & 31, wid = tid >> 5;
    int warpM = wid >> 2, warpN = wid & 3;
    int tileM0 = blockIdx.y * TILE_MN;
    int n0 = blockIdx.x * TILE_MN;

    float acc[4][4][4] = {};

    int rowA = warpM * 64 + (lane & 15);
    int kA   = (lane >> 4) * 8;
    uint32_t xa = (uint32_t)((rowA & 7) << 4);
    int rowB = warpN * 32 + (lane & 7) + ((lane >> 4) << 3);
    int kB   = ((lane >> 3) & 1) * 8;
    uint32_t xb = (uint32_t)((rowB & 7) << 4);

    int lr = tid >> 3;
    int lc = tid & 7;

    const __half* Arow = A + (size_t)tileM0 * KDIM;
    const __half* Wrow = W + (size_t)n0 * KDIM;

    auto load_chunk = [&](int c) {
        uint32_t stage = sb + (uint32_t)((c % 3) * STAGE_BYTES);
        #pragma unroll
        for (int it = 0; it < 4; ++it) {
            int r = lr + it * 32;
            uint32_t off = ((uint32_t)(r * 128 + lc * 16)) ^ ((uint32_t)((r & 7) << 4));
            CP_ASYNC16(stage + off,          Arow + (size_t)r * KDIM + c * KC + lc * 8);
            CP_ASYNC16(stage + 16384 + off,  Wrow + (size_t)r * KDIM + c * KC + lc * 8);
        }
        CP_COMMIT();
    };

    load_chunk(0);
    load_chunk(1);

    #pragma unroll
    for (int c = 0; c < NCHUNK; ++c) {
        if (c == NCHUNK - 1) cp_wait<0>();
        else                 cp_wait<1>();
        __syncthreads();
        // Stage (c+2)%3 was last read in iter c-1; every warp passed that
        // iter's barrier before reaching this point -> safe to overwrite.
        if (c + 2 < NCHUNK) load_chunk(c + 2);

        uint32_t sA = sb + (uint32_t)((c % 3) * STAGE_BYTES);
        uint32_t sB = sA + 16384;
        #pragma unroll
        for (int ks = 0; ks < 4; ++ks) {
            uint32_t a[4][4], b[4][2];
            #pragma unroll
            for (int mt = 0; mt < 4; ++mt) {
                uint32_t addr = sA + ((uint32_t)((rowA + mt * 16) * 128 + ks * 32 + kA * 2) ^ xa);
                ldmatrix_x4(addr, a[mt][0], a[mt][1], a[mt][2], a[mt][3]);
            }
            #pragma unroll
            for (int p = 0; p < 2; ++p) {
                uint32_t addr = sB + ((uint32_t)((rowB + p * 16) * 128 + ks * 32 + kB * 2) ^ xb);
                uint32_t r0, r1, r2, r3;
                ldmatrix_x4(addr, r0, r1, r2, r3);
                b[2 * p][0] = r0;     b[2 * p][1] = r1;
                b[2 * p + 1][0] = r2; b[2 * p + 1][1] = r3;
            }
            #pragma unroll
            for (int mt = 0; mt < 4; ++mt)
                #pragma unroll
                for (int nt = 0; nt < 4; ++nt)
                    mma16816(acc[mt][nt], a[mt], b[nt]);
        }
    }

    #pragma unroll
    for (int mt = 0; mt < 4; ++mt) {
        int m = tileM0 + warpM * 64 + mt * 16 + (lane >> 2);
        #pragma unroll
        for (int nt = 0; nt < 4; ++nt) {
            int n = n0 + warpN * 32 + nt * 8 + (lane & 3) * 2;
            float bx = __ldg(bias + n), by = __ldg(bias + n + 1);
            if (OUTMODE == 0) {
                __half* o = (__half*)Out;
                __half2 h0 = __floats2half2_rn(acc[mt][nt][0] + bx, acc[mt][nt][1] + by);
                __half2 h1 = __floats2half2_rn(acc[mt][nt][2] + bx, acc[mt][nt][3] + by);
                *(__half2*)(o + (size_t)m * ldOut + n) = h0;
                *(__half2*)(o + (size_t)(m + 8) * ldOut + n) = h1;
            } else {
                float* o = (float*)Out;
                *(float2*)(o + pix_offset(m) + n) =
                    make_float2(acc[mt][nt][0] + bx, acc[mt][nt][1] + by);
                *(float2*)(o + pix_offset(m + 8) + n) =
                    make_float2(acc[mt][nt][2] + bx, acc[mt][nt][3] + by);
            }
        }
    }
}

// ---------------------------------------------------------------------------
// Tensor-core attention (unchanged from R6 — proven)
// ---------------------------------------------------------------------------
#define QK_STRIDE 40
#define VT_STRIDE 72

__global__ __launch_bounds__(128) void attn_mma_kernel(const float* __restrict__ table)
{
    __shared__ __align__(16) __half Qs[64 * QK_STRIDE];
    __shared__ __align__(16) __half Ks[64 * QK_STRIDE];
    __shared__ __align__(16) __half Vt[32 * VT_STRIDE];
    __shared__ float bias_s[169];
    __shared__ int   sid_s[49];

    int head = blockIdx.x;
    int win  = blockIdx.y;
    int tid  = threadIdx.x;
    int lane = tid & 31, wid = tid >> 5;

    const __half* qkvh = (const __half*)g_qkvh4;
    size_t base = (size_t)win * NTOK * NQKV + head * HDIM;

    const __half2 sc2 = __floats2half2_rn(0.17677669529663687f, 0.17677669529663687f);
    for (int f = tid; f < 256; f += 128) {
        int r = f >> 2, c = f & 3;
        uint4 qv = make_uint4(0, 0, 0, 0), kv = qv, vv = qv;
        if (r < NTOK) {
            const __half* p = qkvh + base + (size_t)r * NQKV + c * 8;
            qv = *(const uint4*)p;
            kv = *(const uint4*)(p + 384);
            vv = *(const uint4*)(p + 768);
            __half2* qh = (__half2*)&qv;
            #pragma unroll
            for (int t = 0; t < 4; ++t) qh[t] = __hmul2(qh[t], sc2);
        }
        *(uint4*)&Qs[r * QK_STRIDE + c * 8] = qv;
        *(uint4*)&Ks[r * QK_STRIDE + c * 8] = kv;
        const __half* vh = (const __half*)&vv;
        #pragma unroll
        for (int d = 0; d < 8; ++d)
            Vt[(c * 8 + d) * VT_STRIDE + r] = vh[d];
    }
    for (int i = tid; i < 169; i += 128)
        bias_s[i] = table[i * NHEADS + head];
    if (tid < NTOK) {
        int wy = (win & 63) >> 3, wx = win & 7;
        int ty = tid / 7, tx = tid - ty * 7;
        int hreg = (wy < 7) ? 0 : ((ty < 4) ? 1 : 2);
        int wreg = (wx < 7) ? 0 : ((tx < 4) ? 1 : 2);
        sid_s[tid] = hreg * 3 + wreg;
    }
    __syncthreads();

    uint32_t sQ = smem_u32(Qs), sK = smem_u32(Ks), sV = smem_u32(Vt);

    int gid = lane >> 2, tig = lane & 3;
    int rowbase = wid * 16;

    float s[7][4] = {};
    int aRow = rowbase + (lane & 15);
    int aK   = (lane >> 4) * 8;
    int bRow = (lane & 7) + ((lane >> 4) << 3);
    int bK   = ((lane >> 3) & 1) * 8;
    #pragma unroll
    for (int ks = 0; ks < 2; ++ks) {
        uint32_t a[4];
        ldmatrix_x4(sQ + (uint32_t)(aRow * QK_STRIDE + ks * 16 + aK) * 2,
                    a[0], a[1], a[2], a[3]);
        #pragma unroll
        for (int p = 0; p < 4; ++p) {
            uint32_t r0, r1, r2, r3;
            ldmatrix_x4(sK + (uint32_t)((p * 16 + bRow) * QK_STRIDE + ks * 16 + bK) * 2,
                        r0, r1, r2, r3);
            uint32_t b0[2] = {r0, r1}, b1[2] = {r2, r3};
            mma16816(s[2 * p], a, b0);
            if (p < 3) mma16816(s[2 * p + 1], a, b1);
        }
    }

    int r0 = rowbase + gid, r1 = r0 + 8;
    int i0 = (r0 < NTOK) ? r0 : 48;
    int i1 = (r1 < NTOK) ? r1 : 48;
    int iy0 = i0 / 7, ix0 = i0 - iy0 * 7, sd0 = sid_s[i0];
    int iy1 = i1 / 7, ix1 = i1 - iy1 * 7, sd1 = sid_s[i1];

    #pragma unroll
    for (int n = 0; n < 7; ++n) {
        #pragma unroll
        for (int e = 0; e < 2; ++e) {
            int j = n * 8 + tig * 2 + e;
            if (j < NTOK) {
                int jy = j / 7, jx = j - jy * 7;
                int sdj = sid_s[j];
                float b0 = bias_s[(iy0 - jy + 6) * 13 + (ix0 - jx + 6)];
                float b1 = bias_s[(iy1 - jy + 6) * 13 + (ix1 - jx + 6)];
                s[n][e]     += b0 + ((sdj != sd0) ? -100.f : 0.f);
                s[n][2 + e] += b1 + ((sdj != sd1) ? -100.f : 0.f);
            } else {
                s[n][e] = -1e9f;
                s[n][2 + e] = -1e9f;
            }
        }
    }

    float mx0 = -1e30f, mx1 = -1e30f;
    #pragma unroll
    for (int n = 0; n < 7; ++n) {
        mx0 = fmaxf(mx0, fmaxf(s[n][0], s[n][1]));
        mx1 = fmaxf(mx1, fmaxf(s[n][2], s[n][3]));
    }
    mx0 = fmaxf(mx0, __shfl_xor_sync(0xffffffffu, mx0, 1));
    mx0 = fmaxf(mx0, __shfl_xor_sync(0xffffffffu, mx0, 2));
    mx1 = fmaxf(mx1, __shfl_xor_sync(0xffffffffu, mx1, 1));
    mx1 = fmaxf(mx1, __shfl_xor_sync(0xffffffffu, mx1, 2));

    float sm0 = 0.f, sm1 = 0.f;
    #pragma unroll
    for (int n = 0; n < 7; ++n) {
        s[n][0] = __expf(s[n][0] - mx0); sm0 += s[n][0];
        s[n][1] = __expf(s[n][1] - mx0); sm0 += s[n][1];
        s[n][2] = __expf(s[n][2] - mx1); sm1 += s[n][2];
        s[n][3] = __expf(s[n][3] - mx1); sm1 += s[n][3];
    }
    sm0 += __shfl_xor_sync(0xffffffffu, sm0, 1);
    sm0 += __shfl_xor_sync(0xffffffffu, sm0, 2);
    sm1 += __shfl_xor_sync(0xffffffffu, sm1, 1);
    sm1 += __shfl_xor_sync(0xffffffffu, sm1, 2);
    float inv0 = 1.0f / sm0, inv1 = 1.0f / sm1;

    uint32_t aP[4][4];
    #pragma unroll
    for (int kt = 0; kt < 4; ++kt) {
        aP[kt][0] = packh2(s[2 * kt][0], s[2 * kt][1]);
        aP[kt][1] = packh2(s[2 * kt][2], s[2 * kt][3]);
        if (kt < 3) {
            aP[kt][2] = packh2(s[2 * kt + 1][0], s[2 * kt + 1][1]);
            aP[kt][3] = packh2(s[2 * kt + 1][2], s[2 * kt + 1][3]);
        } else {
            aP[kt][2] = 0; aP[kt][3] = 0;
        }
    }

    float o[4][4] = {};
    #pragma unroll
    for (int kt = 0; kt < 4; ++kt) {
        #pragma unroll
        for (int np = 0; np < 2; ++np) {
            uint32_t r0v, r1v, r2v, r3v;
            ldmatrix_x4(sV + (uint32_t)((np * 16 + bRow) * VT_STRIDE + kt * 16 + bK) * 2,
                        r0v, r1v, r2v, r3v);
            uint32_t b0[2] = {r0v, r1v}, b1[2] = {r2v, r3v};
            mma16816(o[2 * np], aP[kt], b0);
            mma16816(o[2 * np + 1], aP[kt], b1);
        }
    }

    __half* att = (__half*)g_atth4;
    #pragma unroll
    for (int nt = 0; nt < 4; ++nt) {
        int col = head * HDIM + nt * 8 + tig * 2;
        if (r0 < NTOK)
            *(__half2*)(att + (size_t)(win * NTOK + r0) * CDIM + col) =
                __floats2half2_rn(o[nt][0] * inv0, o[nt][1] * inv0);
        if (r1 < NTOK)
            *(__half2*)(att + (size_t)(win * NTOK + r1) * CDIM + col) =
                __floats2half2_rn(o[nt][2] * inv1, o[nt][3] * inv1);
    }
}

extern "C" void kernel_launch(void* const* d_in, const int* in_sizes, int n_in,
                              void* d_out, int out_size) {
    const float* x     = (const float*)d_in[0];
    const float* wqkv  = (const float*)d_in[1];
    const float* bqkv  = (const float*)d_in[2];
    const float* wproj = (const float*)d_in[3];
    const float* bproj = (const float*)d_in[4];
    const float* table = (const float*)d_in[5];
    float* out = (float*)d_out;

    __half *xh, *qkvh, *atth, *wqkvh, *wph;
    cudaGetSymbolAddress((void**)&xh,    g_xh4);
    cudaGetSymbolAddress((void**)&qkvh,  g_qkvh4);
    cudaGetSymbolAddress((void**)&atth,  g_atth4);
    cudaGetSymbolAddress((void**)&wqkvh, g_wqkvh4);
    cudaGetSymbolAddress((void**)&wph,   g_wph4);

    cudaFuncSetAttribute(gemm16_kernel<0>,
                         cudaFuncAttributeMaxDynamicSharedMemorySize, SMEM_GEMM);
    cudaFuncSetAttribute(gemm16_kernel<1>,
                         cudaFuncAttributeMaxDynamicSharedMemorySize, SMEM_GEMM);

    convert_gather_x<<<M_TOT * KDIM / 4 / 256, 256>>>(x);
    convert_weights<<<(NQKV + CDIM) * KDIM / 4 / 256, 256>>>(wqkv, wproj);

    gemm16_kernel<0><<<dim3(NQKV / TILE_MN, M_TOT / TILE_MN), 256, SMEM_GEMM>>>(
        xh, wqkvh, bqkv, qkvh, NQKV);
    attn_mma_kernel<<<dim3(NHEADS, WIN_TOT), 128>>>(table);
    gemm16_kernel<1><<<dim3(CDIM / TILE_MN, M_TOT / TILE_MN), 256, SMEM_GEMM>>>(
        atth, wph, bproj, out, 0);
}

// round 8
// speedup vs baseline: 5.9373x; 1.0144x over previous
#include <cuda_runtime.h>
#include <cuda_fp16.h>
#include <cstdint>

#define BATCH     16
#define IMG       56
#define CDIM      384
#define NHEADS    12
#define HDIM      32
#define NTOK      49
#define WIN_TOT   1024
#define M_TOT     50176
#define KDIM      384
#define NQKV      1152

#define TILE_MN   128
#define KC        64
#define NCHUNK    6
#define STAGE_BYTES 32768
#define SMEM_GEMM (3 * STAGE_BYTES)

// fp16 scratch
__device__ uint4 g_xh4   [(size_t)M_TOT * KDIM  / 8];
__device__ uint4 g_qkvh4 [(size_t)M_TOT * NQKV  / 8];
__device__ uint4 g_atth4 [(size_t)M_TOT * CDIM  / 8];
__device__ uint4 g_wqkvh4[(size_t)NQKV  * KDIM  / 8];
__device__ uint4 g_wph4  [(size_t)CDIM  * KDIM  / 8];
// fused bias+mask: [cls][head][i(64)][j(56)]
__device__ float g_bm[4 * NHEADS * 64 * 56];

__device__ __forceinline__ uint32_t smem_u32(const void* p) {
    uint32_t a;
    asm("{ .reg .u64 t; cvta.to.shared.u64 t, %1; cvt.u32.u64 %0, t; }"
        : "=r"(a) : "l"(p));
    return a;
}

__device__ __forceinline__ int pix_offset(int m) {
    int win = m / 49;
    int tok = m - win * 49;
    int b  = win >> 6;
    int wi = win & 63;
    int wy = wi >> 3, wx = wi & 7;
    int ty = tok / 7, tx = tok - ty * 7;
    int h = wy * 7 + ty + 3; if (h >= IMG) h -= IMG;
    int w = wx * 7 + tx + 3; if (w >= IMG) w -= IMG;
    return ((b * IMG + h) * IMG + w) * CDIM;
}

#define CP_ASYNC16(dst, src) \
    asm volatile("cp.async.cg.shared.global [%0], [%1], 16;" :: "r"(dst), "l"(src))
#define CP_COMMIT() asm volatile("cp.async.commit_group;" ::: "memory")
template<int N> __device__ __forceinline__ void cp_wait() {
    asm volatile("cp.async.wait_group %0;" :: "n"(N) : "memory");
}

__device__ __forceinline__ void ldmatrix_x4(uint32_t addr, uint32_t& r0,
                                            uint32_t& r1, uint32_t& r2, uint32_t& r3) {
    asm volatile("ldmatrix.sync.aligned.m8n8.x4.shared.b16 {%0,%1,%2,%3}, [%4];"
                 : "=r"(r0), "=r"(r1), "=r"(r2), "=r"(r3) : "r"(addr));
}

__device__ __forceinline__ void ldmatrix_x4_trans(uint32_t addr, uint32_t& r0,
                                                  uint32_t& r1, uint32_t& r2, uint32_t& r3) {
    asm volatile("ldmatrix.sync.aligned.m8n8.x4.trans.shared.b16 {%0,%1,%2,%3}, [%4];"
                 : "=r"(r0), "=r"(r1), "=r"(r2), "=r"(r3) : "r"(addr));
}

__device__ __forceinline__ void mma16816(float* d, const uint32_t* a, const uint32_t* b) {
    asm volatile(
        "mma.sync.aligned.m16n8k16.row.col.f32.f16.f16.f32 "
        "{%0,%1,%2,%3}, {%4,%5,%6,%7}, {%8,%9}, {%0,%1,%2,%3};"
        : "+f"(d[0]), "+f"(d[1]), "+f"(d[2]), "+f"(d[3])
        : "r"(a[0]), "r"(a[1]), "r"(a[2]), "r"(a[3]), "r"(b[0]), "r"(b[1]));
}

__device__ __forceinline__ uint32_t packh2(float x, float y) {
    __half2 h = __floats2half2_rn(x, y);
    return *(uint32_t*)&h;
}

// ---------------------------------------------------------------------------
// Precompute / converters
// ---------------------------------------------------------------------------
__global__ __launch_bounds__(256) void precompute_bm(const float* __restrict__ table)
{
    int idx = blockIdx.x * 256 + threadIdx.x;      // 4*12*64*56 = 172032
    if (idx >= 4 * NHEADS * 64 * 56) return;
    int j = idx % 56;
    int t = idx / 56;
    int i = t % 64; t /= 64;
    int head = t % NHEADS;
    int cls = t / NHEADS;
    float v;
    if (j < 49) {
        int ie = (i < 49) ? i : 48;
        int iy = ie / 7, ix = ie % 7, jy = j / 7, jx = j % 7;
        float bias = table[((iy - jy + 6) * 13 + (ix - jx + 6)) * NHEADS + head];
        int clsh = cls >> 1, clsw = cls & 1;
        int hi = clsh ? ((iy < 4) ? 1 : 2) : 0;
        int wi = clsw ? ((ix < 4) ? 1 : 2) : 0;
        int hj = clsh ? ((jy < 4) ? 1 : 2) : 0;
        int wj = clsw ? ((jx < 4) ? 1 : 2) : 0;
        v = bias + (((hi * 3 + wi) != (hj * 3 + wj)) ? -100.0f : 0.0f);
    } else {
        v = -1e9f;
    }
    g_bm[idx] = v;
}

__global__ __launch_bounds__(256) void convert_gather_x(const float* __restrict__ x)
{
    __half* dst = (__half*)g_xh4;
    int i4 = blockIdx.x * 256 + threadIdx.x;
    int m  = i4 / 96, k4 = (i4 % 96) * 4;
    float4 v = *(const float4*)(x + pix_offset(m) + k4);
    __half2 h0 = __floats2half2_rn(v.x, v.y);
    __half2 h1 = __floats2half2_rn(v.z, v.w);
    *(uint2*)(dst + (size_t)m * KDIM + k4) =
        make_uint2(*(uint32_t*)&h0, *(uint32_t*)&h1);
}

__global__ __launch_bounds__(256) void convert_weights(
    const float* __restrict__ wqkv, const float* __restrict__ wproj)
{
    int i4 = (blockIdx.x * 256 + threadIdx.x) * 4;
    const float* s;
    __half* d;
    if (i4 < NQKV * KDIM) {
        s = wqkv + i4;
        d = (__half*)g_wqkvh4 + i4;
    } else {
        s = wproj + (i4 - NQKV * KDIM);
        d = (__half*)g_wph4 + (i4 - NQKV * KDIM);
    }
    float4 v = *(const float4*)s;
    __half2 h0 = __floats2half2_rn(v.x, v.y);
    __half2 h1 = __floats2half2_rn(v.z, v.w);
    *(uint2*)d = make_uint2(*(uint32_t*)&h0, *(uint32_t*)&h1);
}

// ---------------------------------------------------------------------------
// fp16 GEMM, cp.async 3-stage pipeline, one barrier per chunk (R7 — proven)
// ---------------------------------------------------------------------------
template<int OUTMODE>
__global__ __launch_bounds__(256) void gemm16_kernel(
    const __half* __restrict__ A, const __half* __restrict__ W,
    const float* __restrict__ bias, void* __restrict__ Out, int ldOut)
{
    extern __shared__ __align__(128) char smem[];
    uint32_t sb = smem_u32(smem);

    int tid  = threadIdx.x;
    int lane = tid & 31, wid = tid >> 5;
    int warpM = wid >> 2, warpN = wid & 3;
    int tileM0 = blockIdx.y * TILE_MN;
    int n0 = blockIdx.x * TILE_MN;

    float acc[4][4][4] = {};

    int rowA = warpM * 64 + (lane & 15);
    int kA   = (lane >> 4) * 8;
    uint32_t xa = (uint32_t)((rowA & 7) << 4);
    int rowB = warpN * 32 + (lane & 7) + ((lane >> 4) << 3);
    int kB   = ((lane >> 3) & 1) * 8;
    uint32_t xb = (uint32_t)((rowB & 7) << 4);

    int lr = tid >> 3;
    int lc = tid & 7;

    const __half* Arow = A + (size_t)tileM0 * KDIM;
    const __half* Wrow = W + (size_t)n0 * KDIM;

    auto load_chunk = [&](int c) {
        uint32_t stage = sb + (uint32_t)((c % 3) * STAGE_BYTES);
        #pragma unroll
        for (int it = 0; it < 4; ++it) {
            int r = lr + it * 32;
            uint32_t off = ((uint32_t)(r * 128 + lc * 16)) ^ ((uint32_t)((r & 7) << 4));
            CP_ASYNC16(stage + off,          Arow + (size_t)r * KDIM + c * KC + lc * 8);
            CP_ASYNC16(stage + 16384 + off,  Wrow + (size_t)r * KDIM + c * KC + lc * 8);
        }
        CP_COMMIT();
    };

    load_chunk(0);
    load_chunk(1);

    #pragma unroll
    for (int c = 0; c < NCHUNK; ++c) {
        if (c == NCHUNK - 1) cp_wait<0>();
        else                 cp_wait<1>();
        __syncthreads();
        if (c + 2 < NCHUNK) load_chunk(c + 2);

        uint32_t sA = sb + (uint32_t)((c % 3) * STAGE_BYTES);
        uint32_t sB = sA + 16384;
        #pragma unroll
        for (int ks = 0; ks < 4; ++ks) {
            uint32_t a[4][4], b[4][2];
            #pragma unroll
            for (int mt = 0; mt < 4; ++mt) {
                uint32_t addr = sA + ((uint32_t)((rowA + mt * 16) * 128 + ks * 32 + kA * 2) ^ xa);
                ldmatrix_x4(addr, a[mt][0], a[mt][1], a[mt][2], a[mt][3]);
            }
            #pragma unroll
            for (int p = 0; p < 2; ++p) {
                uint32_t addr = sB + ((uint32_t)((rowB + p * 16) * 128 + ks * 32 + kB * 2) ^ xb);
                uint32_t r0, r1, r2, r3;
                ldmatrix_x4(addr, r0, r1, r2, r3);
                b[2 * p][0] = r0;     b[2 * p][1] = r1;
                b[2 * p + 1][0] = r2; b[2 * p + 1][1] = r3;
            }
            #pragma unroll
            for (int mt = 0; mt < 4; ++mt)
                #pragma unroll
                for (int nt = 0; nt < 4; ++nt)
                    mma16816(acc[mt][nt], a[mt], b[nt]);
        }
    }

    #pragma unroll
    for (int mt = 0; mt < 4; ++mt) {
        int m = tileM0 + warpM * 64 + mt * 16 + (lane >> 2);
        #pragma unroll
        for (int nt = 0; nt < 4; ++nt) {
            int n = n0 + warpN * 32 + nt * 8 + (lane & 3) * 2;
            float bx = __ldg(bias + n), by = __ldg(bias + n + 1);
            if (OUTMODE == 0) {
                __half* o = (__half*)Out;
                __half2 h0 = __floats2half2_rn(acc[mt][nt][0] + bx, acc[mt][nt][1] + by);
                __half2 h1 = __floats2half2_rn(acc[mt][nt][2] + bx, acc[mt][nt][3] + by);
                *(__half2*)(o + (size_t)m * ldOut + n) = h0;
                *(__half2*)(o + (size_t)(m + 8) * ldOut + n) = h1;
            } else {
                float* o = (float*)Out;
                *(float2*)(o + pix_offset(m) + n) =
                    make_float2(acc[mt][nt][0] + bx, acc[mt][nt][1] + by);
                *(float2*)(o + pix_offset(m + 8) + n) =
                    make_float2(acc[mt][nt][2] + bx, acc[mt][nt][3] + by);
            }
        }
    }
}

// ---------------------------------------------------------------------------
// Tensor-core attention, ALU-light version:
//  - bias+mask fused in precomputed g_bm (direct float2 loads, no index math)
//  - V stored row-major like K; B-fragments via ldmatrix.trans (no smem
//    transpose scatter)
// ---------------------------------------------------------------------------
#define QK_STRIDE 40     // halves per row (80B: conflict-free 5i mod 8)

__global__ __launch_bounds__(128) void attn_mma_kernel()
{
    __shared__ __align__(16) __half Qs[64 * QK_STRIDE];
    __shared__ __align__(16) __half Ks[64 * QK_STRIDE];
    __shared__ __align__(16) __half Vs[64 * QK_STRIDE];

    int head = blockIdx.x;
    int win  = blockIdx.y;
    int tid  = threadIdx.x;
    int lane = tid & 31, wid = tid >> 5;

    const __half* qkvh = (const __half*)g_qkvh4;
    size_t base = (size_t)win * NTOK * NQKV + head * HDIM;

    const __half2 sc2 = __floats2half2_rn(0.17677669529663687f, 0.17677669529663687f);
    #pragma unroll
    for (int f = tid; f < 256; f += 128) {
        int r = f >> 2, c = f & 3;
        uint4 qv = make_uint4(0, 0, 0, 0), kv = qv, vv = qv;
        if (r < NTOK) {
            const __half* p = qkvh + base + (size_t)r * NQKV + c * 8;
            qv = *(const uint4*)p;
            kv = *(const uint4*)(p + 384);
            vv = *(const uint4*)(p + 768);
            __half2* qh = (__half2*)&qv;
            #pragma unroll
            for (int t = 0; t < 4; ++t) qh[t] = __hmul2(qh[t], sc2);
        }
        *(uint4*)&Qs[r * QK_STRIDE + c * 8] = qv;
        *(uint4*)&Ks[r * QK_STRIDE + c * 8] = kv;
        *(uint4*)&Vs[r * QK_STRIDE + c * 8] = vv;
    }
    __syncthreads();

    uint32_t sQ = smem_u32(Qs), sK = smem_u32(Ks), sV = smem_u32(Vs);

    int gid = lane >> 2, tig = lane & 3;
    int rowbase = wid * 16;

    // ---- S = Q K^T
    float s[7][4] = {};
    int aRow = rowbase + (lane & 15);
    int aK   = (lane >> 4) * 8;
    int bRow = (lane & 7) + ((lane >> 4) << 3);
    int bK   = ((lane >> 3) & 1) * 8;
    #pragma unroll
    for (int ks = 0; ks < 2; ++ks) {
        uint32_t a[4];
        ldmatrix_x4(sQ + (uint32_t)(aRow * QK_STRIDE + ks * 16 + aK) * 2,
                    a[0], a[1], a[2], a[3]);
        #pragma unroll
        for (int p = 0; p < 4; ++p) {
            uint32_t r0, r1, r2, r3;
            ldmatrix_x4(sK + (uint32_t)((p * 16 + bRow) * QK_STRIDE + ks * 16 + bK) * 2,
                        r0, r1, r2, r3);
            uint32_t b0[2] = {r0, r1}, b1[2] = {r2, r3};
            mma16816(s[2 * p], a, b0);
            if (p < 3) mma16816(s[2 * p + 1], a, b1);
        }
    }

    // ---- fused bias+mask from precomputed table
    int r0 = rowbase + gid, r1 = r0 + 8;
    int wy = (win & 63) >> 3, wx = win & 7;
    int cls = ((wy == 7) ? 2 : 0) + ((wx == 7) ? 1 : 0);
    const float* bmBase = g_bm + (size_t)(cls * NHEADS + head) * 64 * 56;
    const float* bm0 = bmBase + r0 * 56 + tig * 2;
    const float* bm1 = bmBase + r1 * 56 + tig * 2;
    #pragma unroll
    for (int n = 0; n < 7; ++n) {
        float2 b0 = *(const float2*)(bm0 + n * 8);
        float2 b1 = *(const float2*)(bm1 + n * 8);
        s[n][0] += b0.x; s[n][1] += b0.y;
        s[n][2] += b1.x; s[n][3] += b1.y;
    }

    // ---- softmax on fragments
    float mx0 = -1e30f, mx1 = -1e30f;
    #pragma unroll
    for (int n = 0; n < 7; ++n) {
        mx0 = fmaxf(mx0, fmaxf(s[n][0], s[n][1]));
        mx1 = fmaxf(mx1, fmaxf(s[n][2], s[n][3]));
    }
    mx0 = fmaxf(mx0, __shfl_xor_sync(0xffffffffu, mx0, 1));
    mx0 = fmaxf(mx0, __shfl_xor_sync(0xffffffffu, mx0, 2));
    mx1 = fmaxf(mx1, __shfl_xor_sync(0xffffffffu, mx1, 1));
    mx1 = fmaxf(mx1, __shfl_xor_sync(0xffffffffu, mx1, 2));

    float sm0 = 0.f, sm1 = 0.f;
    #pragma unroll
    for (int n = 0; n < 7; ++n) {
        s[n][0] = __expf(s[n][0] - mx0); sm0 += s[n][0];
        s[n][1] = __expf(s[n][1] - mx0); sm0 += s[n][1];
        s[n][2] = __expf(s[n][2] - mx1); sm1 += s[n][2];
        s[n][3] = __expf(s[n][3] - mx1); sm1 += s[n][3];
    }
    sm0 += __shfl_xor_sync(0xffffffffu, sm0, 1);
    sm0 += __shfl_xor_sync(0xffffffffu, sm0, 2);
    sm1 += __shfl_xor_sync(0xffffffffu, sm1, 1);
    sm1 += __shfl_xor_sync(0xffffffffu, sm1, 2);
    float inv0 = 1.0f / sm0, inv1 = 1.0f / sm1;

    // ---- P fragments (fp16, unnormalized)
    uint32_t aP[4][4];
    #pragma unroll
    for (int kt = 0; kt < 4; ++kt) {
        aP[kt][0] = packh2(s[2 * kt][0], s[2 * kt][1]);
        aP[kt][1] = packh2(s[2 * kt][2], s[2 * kt][3]);
        if (kt < 3) {
            aP[kt][2] = packh2(s[2 * kt + 1][0], s[2 * kt + 1][1]);
            aP[kt][3] = packh2(s[2 * kt + 1][2], s[2 * kt + 1][3]);
        } else {
            aP[kt][2] = 0; aP[kt][3] = 0;
        }
    }

    // ---- O = P V : B-fragments via ldmatrix.trans on row-major V
    float o[4][4] = {};
    int vRow = lane & 15;
    int vCol = (lane >> 4) << 3;
    #pragma unroll
    for (int kt = 0; kt < 4; ++kt) {
        #pragma unroll
        for (int np = 0; np < 2; ++np) {
            uint32_t r0v, r1v, r2v, r3v;
            uint32_t addr = sV + (uint32_t)((kt * 16 + vRow) * QK_STRIDE + np * 16 + vCol) * 2;
            ldmatrix_x4_trans(addr, r0v, r1v, r2v, r3v);
            uint32_t b0[2] = {r0v, r1v}, b1[2] = {r2v, r3v};
            mma16816(o[2 * np], aP[kt], b0);
            mma16816(o[2 * np + 1], aP[kt], b1);
        }
    }

    // ---- store O (fp16) with fp32 normalization
    __half* att = (__half*)g_atth4;
    #pragma unroll
    for (int nt = 0; nt < 4; ++nt) {
        int col = head * HDIM + nt * 8 + tig * 2;
        if (r0 < NTOK)
            *(__half2*)(att + (size_t)(win * NTOK + r0) * CDIM + col) =
                __floats2half2_rn(o[nt][0] * inv0, o[nt][1] * inv0);
        if (r1 < NTOK)
            *(__half2*)(att + (size_t)(win * NTOK + r1) * CDIM + col) =
                __floats2half2_rn(o[nt][2] * inv1, o[nt][3] * inv1);
    }
}

extern "C" void kernel_launch(void* const* d_in, const int* in_sizes, int n_in,
                              void* d_out, int out_size) {
    const float* x     = (const float*)d_in[0];
    const float* wqkv  = (const float*)d_in[1];
    const float* bqkv  = (const float*)d_in[2];
    const float* wproj = (const float*)d_in[3];
    const float* bproj = (const float*)d_in[4];
    const float* table = (const float*)d_in[5];
    float* out = (float*)d_out;

    __half *xh, *qkvh, *atth, *wqkvh, *wph;
    cudaGetSymbolAddress((void**)&xh,    g_xh4);
    cudaGetSymbolAddress((void**)&qkvh,  g_qkvh4);
    cudaGetSymbolAddress((void**)&atth,  g_atth4);
    cudaGetSymbolAddress((void**)&wqkvh, g_wqkvh4);
    cudaGetSymbolAddress((void**)&wph,   g_wph4);

    cudaFuncSetAttribute(gemm16_kernel<0>,
                         cudaFuncAttributeMaxDynamicSharedMemorySize, SMEM_GEMM);
    cudaFuncSetAttribute(gemm16_kernel<1>,
                         cudaFuncAttributeMaxDynamicSharedMemorySize, SMEM_GEMM);

    precompute_bm<<<(4 * NHEADS * 64 * 56 + 255) / 256, 256>>>(table);
    convert_gather_x<<<M_TOT * KDIM / 4 / 256, 256>>>(x);
    convert_weights<<<(NQKV + CDIM) * KDIM / 4 / 256, 256>>>(wqkv, wproj);

    gemm16_kernel<0><<<dim3(NQKV / TILE_MN, M_TOT / TILE_MN), 256, SMEM_GEMM>>>(
        xh, wqkvh, bqkv, qkvh, NQKV);
    attn_mma_kernel<<<dim3(NHEADS, WIN_TOT), 128>>>();
    gemm16_kernel<1><<<dim3(CDIM / TILE_MN, M_TOT / TILE_MN), 256, SMEM_GEMM>>>(
        atth, wph, bproj, out, 0);
}

// round 9
// speedup vs baseline: 6.7565x; 1.1380x over previous
#include <cuda_runtime.h>
#include <cuda_fp16.h>
#include <cstdint>

#define BATCH     16
#define IMG       56
#define CDIM      384
#define NHEADS    12
#define HDIM      32
#define NTOK      49
#define WIN_TOT   1024
#define M_TOT     50176
#define KDIM      384
#define NQKV      1152

#define TILE_MN   128
#define KC        64
#define NCHUNK    6
#define STAGE_BYTES 32768
#define SMEM_GEMM (3 * STAGE_BYTES)

// fp16 scratch
__device__ uint4 g_xh4   [(size_t)M_TOT * KDIM  / 8];
__device__ uint4 g_qkvh4 [(size_t)M_TOT * NQKV  / 8];
__device__ uint4 g_atth4 [(size_t)M_TOT * CDIM  / 8];
__device__ uint4 g_wqkvh4[(size_t)NQKV  * KDIM  / 8];
__device__ uint4 g_wph4  [(size_t)CDIM  * KDIM  / 8];
// fused bias+mask: [cls][head][i(64)][j(56)]
__device__ float g_bm[4 * NHEADS * 64 * 56];

__device__ __forceinline__ uint32_t smem_u32(const void* p) {
    uint32_t a;
    asm("{ .reg .u64 t; cvta.to.shared.u64 t, %1; cvt.u32.u64 %0, t; }"
        : "=r"(a) : "l"(p));
    return a;
}

__device__ __forceinline__ int pix_offset(int m) {
    int win = m / 49;
    int tok = m - win * 49;
    int b  = win >> 6;
    int wi = win & 63;
    int wy = wi >> 3, wx = wi & 7;
    int ty = tok / 7, tx = tok - ty * 7;
    int h = wy * 7 + ty + 3; if (h >= IMG) h -= IMG;
    int w = wx * 7 + tx + 3; if (w >= IMG) w -= IMG;
    return ((b * IMG + h) * IMG + w) * CDIM;
}

#define CP_ASYNC16(dst, src) \
    asm volatile("cp.async.cg.shared.global [%0], [%1], 16;" :: "r"(dst), "l"(src))
#define CP_COMMIT() asm volatile("cp.async.commit_group;" ::: "memory")
template<int N> __device__ __forceinline__ void cp_wait() {
    asm volatile("cp.async.wait_group %0;" :: "n"(N) : "memory");
}

__device__ __forceinline__ void ldmatrix_x4(uint32_t addr, uint32_t& r0,
                                            uint32_t& r1, uint32_t& r2, uint32_t& r3) {
    asm volatile("ldmatrix.sync.aligned.m8n8.x4.shared.b16 {%0,%1,%2,%3}, [%4];"
                 : "=r"(r0), "=r"(r1), "=r"(r2), "=r"(r3) : "r"(addr));
}

__device__ __forceinline__ void ldmatrix_x4_trans(uint32_t addr, uint32_t& r0,
                                                  uint32_t& r1, uint32_t& r2, uint32_t& r3) {
    asm volatile("ldmatrix.sync.aligned.m8n8.x4.trans.shared.b16 {%0,%1,%2,%3}, [%4];"
                 : "=r"(r0), "=r"(r1), "=r"(r2), "=r"(r3) : "r"(addr));
}

__device__ __forceinline__ void mma16816(float* d, const uint32_t* a, const uint32_t* b) {
    asm volatile(
        "mma.sync.aligned.m16n8k16.row.col.f32.f16.f16.f32 "
        "{%0,%1,%2,%3}, {%4,%5,%6,%7}, {%8,%9}, {%0,%1,%2,%3};"
        : "+f"(d[0]), "+f"(d[1]), "+f"(d[2]), "+f"(d[3])
        : "r"(a[0]), "r"(a[1]), "r"(a[2]), "r"(a[3]), "r"(b[0]), "r"(b[1]));
}

__device__ __forceinline__ uint32_t packh2(float x, float y) {
    __half2 h = __floats2half2_rn(x, y);
    return *(uint32_t*)&h;
}

// ---------------------------------------------------------------------------
// Precompute / converters
// ---------------------------------------------------------------------------
__global__ __launch_bounds__(256) void precompute_bm(const float* __restrict__ table)
{
    int idx = blockIdx.x * 256 + threadIdx.x;
    if (idx >= 4 * NHEADS * 64 * 56) return;
    int j = idx % 56;
    int t = idx / 56;
    int i = t % 64; t /= 64;
    int head = t % NHEADS;
    int cls = t / NHEADS;
    float v;
    if (j < 49) {
        int ie = (i < 49) ? i : 48;
        int iy = ie / 7, ix = ie % 7, jy = j / 7, jx = j % 7;
        float bias = table[((iy - jy + 6) * 13 + (ix - jx + 6)) * NHEADS + head];
        int clsh = cls >> 1, clsw = cls & 1;
        int hi = clsh ? ((iy < 4) ? 1 : 2) : 0;
        int wi = clsw ? ((ix < 4) ? 1 : 2) : 0;
        int hj = clsh ? ((jy < 4) ? 1 : 2) : 0;
        int wj = clsw ? ((jx < 4) ? 1 : 2) : 0;
        v = bias + (((hi * 3 + wi) != (hj * 3 + wj)) ? -100.0f : 0.0f);
    } else {
        v = -1e9f;
    }
    g_bm[idx] = v;
}

__global__ __launch_bounds__(256) void convert_gather_x(const float* __restrict__ x)
{
    __half* dst = (__half*)g_xh4;
    int i4 = blockIdx.x * 256 + threadIdx.x;
    int m  = i4 / 96, k4 = (i4 % 96) * 4;
    float4 v = *(const float4*)(x + pix_offset(m) + k4);
    __half2 h0 = __floats2half2_rn(v.x, v.y);
    __half2 h1 = __floats2half2_rn(v.z, v.w);
    *(uint2*)(dst + (size_t)m * KDIM + k4) =
        make_uint2(*(uint32_t*)&h0, *(uint32_t*)&h1);
}

__global__ __launch_bounds__(256) void convert_weights(
    const float* __restrict__ wqkv, const float* __restrict__ wproj)
{
    int i4 = (blockIdx.x * 256 + threadIdx.x) * 4;
    const float* s;
    __half* d;
    if (i4 < NQKV * KDIM) {
        s = wqkv + i4;
        d = (__half*)g_wqkvh4 + i4;
    } else {
        s = wproj + (i4 - NQKV * KDIM);
        d = (__half*)g_wph4 + (i4 - NQKV * KDIM);
    }
    float4 v = *(const float4*)s;
    __half2 h0 = __floats2half2_rn(v.x, v.y);
    __half2 h1 = __floats2half2_rn(v.z, v.w);
    *(uint2*)d = make_uint2(*(uint32_t*)&h0, *(uint32_t*)&h1);
}

// ---------------------------------------------------------------------------
// fp16 GEMM, cp.async 3-stage pipeline, one barrier per chunk.
// __launch_bounds__(256, 2): pin 2 CTAs/SM (<=128 regs) — the R8 regression
// was regs creeping to 132 and halving occupancy.
// ---------------------------------------------------------------------------
template<int OUTMODE>
__global__ __launch_bounds__(256, 2) void gemm16_kernel(
    const __half* __restrict__ A, const __half* __restrict__ W,
    const float* __restrict__ bias, void* __restrict__ Out, int ldOut)
{
    extern __shared__ __align__(128) char smem[];
    uint32_t sb = smem_u32(smem);

    int tid  = threadIdx.x;
    int lane = tid & 31, wid = tid >> 5;
    int warpM = wid >> 2, warpN = wid & 3;
    int tileM0 = blockIdx.y * TILE_MN;
    int n0 = blockIdx.x * TILE_MN;

    float acc[4][4][4] = {};

    int rowA = warpM * 64 + (lane & 15);
    int kA   = (lane >> 4) * 8;
    uint32_t xa = (uint32_t)((rowA & 7) << 4);
    int rowB = warpN * 32 + (lane & 7) + ((lane >> 4) << 3);
    int kB   = ((lane >> 3) & 1) * 8;
    uint32_t xb = (uint32_t)((rowB & 7) << 4);

    int lr = tid >> 3;
    int lc = tid & 7;

    const __half* Arow = A + (size_t)tileM0 * KDIM;
    const __half* Wrow = W + (size_t)n0 * KDIM;

    auto load_chunk = [&](int c) {
        uint32_t stage = sb + (uint32_t)((c % 3) * STAGE_BYTES);
        #pragma unroll
        for (int it = 0; it < 4; ++it) {
            int r = lr + it * 32;
            uint32_t off = ((uint32_t)(r * 128 + lc * 16)) ^ ((uint32_t)((r & 7) << 4));
            CP_ASYNC16(stage + off,          Arow + (size_t)r * KDIM + c * KC + lc * 8);
            CP_ASYNC16(stage + 16384 + off,  Wrow + (size_t)r * KDIM + c * KC + lc * 8);
        }
        CP_COMMIT();
    };

    load_chunk(0);
    load_chunk(1);

    #pragma unroll
    for (int c = 0; c < NCHUNK; ++c) {
        if (c == NCHUNK - 1) cp_wait<0>();
        else                 cp_wait<1>();
        __syncthreads();
        if (c + 2 < NCHUNK) load_chunk(c + 2);

        uint32_t sA = sb + (uint32_t)((c % 3) * STAGE_BYTES);
        uint32_t sB = sA + 16384;
        #pragma unroll
        for (int ks = 0; ks < 4; ++ks) {
            uint32_t a[4][4], b[4][2];
            #pragma unroll
            for (int mt = 0; mt < 4; ++mt) {
                uint32_t addr = sA + ((uint32_t)((rowA + mt * 16) * 128 + ks * 32 + kA * 2) ^ xa);
                ldmatrix_x4(addr, a[mt][0], a[mt][1], a[mt][2], a[mt][3]);
            }
            #pragma unroll
            for (int p = 0; p < 2; ++p) {
                uint32_t addr = sB + ((uint32_t)((rowB + p * 16) * 128 + ks * 32 + kB * 2) ^ xb);
                uint32_t r0, r1, r2, r3;
                ldmatrix_x4(addr, r0, r1, r2, r3);
                b[2 * p][0] = r0;     b[2 * p][1] = r1;
                b[2 * p + 1][0] = r2; b[2 * p + 1][1] = r3;
            }
            #pragma unroll
            for (int mt = 0; mt < 4; ++mt)
                #pragma unroll
                for (int nt = 0; nt < 4; ++nt)
                    mma16816(acc[mt][nt], a[mt], b[nt]);
        }
    }

    #pragma unroll
    for (int mt = 0; mt < 4; ++mt) {
        int m = tileM0 + warpM * 64 + mt * 16 + (lane >> 2);
        #pragma unroll
        for (int nt = 0; nt < 4; ++nt) {
            int n = n0 + warpN * 32 + nt * 8 + (lane & 3) * 2;
            float bx = __ldg(bias + n), by = __ldg(bias + n + 1);
            if (OUTMODE == 0) {
                __half* o = (__half*)Out;
                __half2 h0 = __floats2half2_rn(acc[mt][nt][0] + bx, acc[mt][nt][1] + by);
                __half2 h1 = __floats2half2_rn(acc[mt][nt][2] + bx, acc[mt][nt][3] + by);
                *(__half2*)(o + (size_t)m * ldOut + n) = h0;
                *(__half2*)(o + (size_t)(m + 8) * ldOut + n) = h1;
            } else {
                float* o = (float*)Out;
                *(float2*)(o + pix_offset(m) + n) =
                    make_float2(acc[mt][nt][0] + bx, acc[mt][nt][1] + by);
                *(float2*)(o + pix_offset(m + 8) + n) =
                    make_float2(acc[mt][nt][2] + bx, acc[mt][nt][3] + by);
            }
        }
    }
}

// ---------------------------------------------------------------------------
// Tensor-core attention (R8 — proven): precomputed bias+mask, ldmatrix.trans V
// ---------------------------------------------------------------------------
#define QK_STRIDE 40

__global__ __launch_bounds__(128) void attn_mma_kernel()
{
    __shared__ __align__(16) __half Qs[64 * QK_STRIDE];
    __shared__ __align__(16) __half Ks[64 * QK_STRIDE];
    __shared__ __align__(16) __half Vs[64 * QK_STRIDE];

    int head = blockIdx.x;
    int win  = blockIdx.y;
    int tid  = threadIdx.x;
    int lane = tid & 31, wid = tid >> 5;

    const __half* qkvh = (const __half*)g_qkvh4;
    size_t base = (size_t)win * NTOK * NQKV + head * HDIM;

    const __half2 sc2 = __floats2half2_rn(0.17677669529663687f, 0.17677669529663687f);
    #pragma unroll
    for (int f = tid; f < 256; f += 128) {
        int r = f >> 2, c = f & 3;
        uint4 qv = make_uint4(0, 0, 0, 0), kv = qv, vv = qv;
        if (r < NTOK) {
            const __half* p = qkvh + base + (size_t)r * NQKV + c * 8;
            qv = *(const uint4*)p;
            kv = *(const uint4*)(p + 384);
            vv = *(const uint4*)(p + 768);
            __half2* qh = (__half2*)&qv;
            #pragma unroll
            for (int t = 0; t < 4; ++t) qh[t] = __hmul2(qh[t], sc2);
        }
        *(uint4*)&Qs[r * QK_STRIDE + c * 8] = qv;
        *(uint4*)&Ks[r * QK_STRIDE + c * 8] = kv;
        *(uint4*)&Vs[r * QK_STRIDE + c * 8] = vv;
    }
    __syncthreads();

    uint32_t sQ = smem_u32(Qs), sK = smem_u32(Ks), sV = smem_u32(Vs);

    int gid = lane >> 2, tig = lane & 3;
    int rowbase = wid * 16;

    float s[7][4] = {};
    int aRow = rowbase + (lane & 15);
    int aK   = (lane >> 4) * 8;
    int bRow = (lane & 7) + ((lane >> 4) << 3);
    int bK   = ((lane >> 3) & 1) * 8;
    #pragma unroll
    for (int ks = 0; ks < 2; ++ks) {
        uint32_t a[4];
        ldmatrix_x4(sQ + (uint32_t)(aRow * QK_STRIDE + ks * 16 + aK) * 2,
                    a[0], a[1], a[2], a[3]);
        #pragma unroll
        for (int p = 0; p < 4; ++p) {
            uint32_t r0, r1, r2, r3;
            ldmatrix_x4(sK + (uint32_t)((p * 16 + bRow) * QK_STRIDE + ks * 16 + bK) * 2,
                        r0, r1, r2, r3);
            uint32_t b0[2] = {r0, r1}, b1[2] = {r2, r3};
            mma16816(s[2 * p], a, b0);
            if (p < 3) mma16816(s[2 * p + 1], a, b1);
        }
    }

    int r0 = rowbase + gid, r1 = r0 + 8;
    int wy = (win & 63) >> 3, wx = win & 7;
    int cls = ((wy == 7) ? 2 : 0) + ((wx == 7) ? 1 : 0);
    const float* bmBase = g_bm + (size_t)(cls * NHEADS + head) * 64 * 56;
    const float* bm0 = bmBase + r0 * 56 + tig * 2;
    const float* bm1 = bmBase + r1 * 56 + tig * 2;
    #pragma unroll
    for (int n = 0; n < 7; ++n) {
        float2 b0 = *(const float2*)(bm0 + n * 8);
        float2 b1 = *(const float2*)(bm1 + n * 8);
        s[n][0] += b0.x; s[n][1] += b0.y;
        s[n][2] += b1.x; s[n][3] += b1.y;
    }

    float mx0 = -1e30f, mx1 = -1e30f;
    #pragma unroll
    for (int n = 0; n < 7; ++n) {
        mx0 = fmaxf(mx0, fmaxf(s[n][0], s[n][1]));
        mx1 = fmaxf(mx1, fmaxf(s[n][2], s[n][3]));
    }
    mx0 = fmaxf(mx0, __shfl_xor_sync(0xffffffffu, mx0, 1));
    mx0 = fmaxf(mx0, __shfl_xor_sync(0xffffffffu, mx0, 2));
    mx1 = fmaxf(mx1, __shfl_xor_sync(0xffffffffu, mx1, 1));
    mx1 = fmaxf(mx1, __shfl_xor_sync(0xffffffffu, mx1, 2));

    float sm0 = 0.f, sm1 = 0.f;
    #pragma unroll
    for (int n = 0; n < 7; ++n) {
        s[n][0] = __expf(s[n][0] - mx0); sm0 += s[n][0];
        s[n][1] = __expf(s[n][1] - mx0); sm0 += s[n][1];
        s[n][2] = __expf(s[n][2] - mx1); sm1 += s[n][2];
        s[n][3] = __expf(s[n][3] - mx1); sm1 += s[n][3];
    }
    sm0 += __shfl_xor_sync(0xffffffffu, sm0, 1);
    sm0 += __shfl_xor_sync(0xffffffffu, sm0, 2);
    sm1 += __shfl_xor_sync(0xffffffffu, sm1, 1);
    sm1 += __shfl_xor_sync(0xffffffffu, sm1, 2);
    float inv0 = 1.0f / sm0, inv1 = 1.0f / sm1;

    uint32_t aP[4][4];
    #pragma unroll
    for (int kt = 0; kt < 4; ++kt) {
        aP[kt][0] = packh2(s[2 * kt][0], s[2 * kt][1]);
        aP[kt][1] = packh2(s[2 * kt][2], s[2 * kt][3]);
        if (kt < 3) {
            aP[kt][2] = packh2(s[2 * kt + 1][0], s[2 * kt + 1][1]);
            aP[kt][3] = packh2(s[2 * kt + 1][2], s[2 * kt + 1][3]);
        } else {
            aP[kt][2] = 0; aP[kt][3] = 0;
        }
    }

    float o[4][4] = {};
    int vRow = lane & 15;
    int vCol = (lane >> 4) << 3;
    #pragma unroll
    for (int kt = 0; kt < 4; ++kt) {
        #pragma unroll
        for (int np = 0; np < 2; ++np) {
            uint32_t r0v, r1v, r2v, r3v;
            uint32_t addr = sV + (uint32_t)((kt * 16 + vRow) * QK_STRIDE + np * 16 + vCol) * 2;
            ldmatrix_x4_trans(addr, r0v, r1v, r2v, r3v);
            uint32_t b0[2] = {r0v, r1v}, b1[2] = {r2v, r3v};
            mma16816(o[2 * np], aP[kt], b0);
            mma16816(o[2 * np + 1], aP[kt], b1);
        }
    }

    __half* att = (__half*)g_atth4;
    #pragma unroll
    for (int nt = 0; nt < 4; ++nt) {
        int col = head * HDIM + nt * 8 + tig * 2;
        if (r0 < NTOK)
            *(__half2*)(att + (size_t)(win * NTOK + r0) * CDIM + col) =
                __floats2half2_rn(o[nt][0] * inv0, o[nt][1] * inv0);
        if (r1 < NTOK)
            *(__half2*)(att + (size_t)(win * NTOK + r1) * CDIM + col) =
                __floats2half2_rn(o[nt][2] * inv1, o[nt][3] * inv1);
    }
}

extern "C" void kernel_launch(void* const* d_in, const int* in_sizes, int n_in,
                              void* d_out, int out_size) {
    const float* x     = (const float*)d_in[0];
    const float* wqkv  = (const float*)d_in[1];
    const float* bqkv  = (const float*)d_in[2];
    const float* wproj = (const float*)d_in[3];
    const float* bproj = (const float*)d_in[4];
    const float* table = (const float*)d_in[5];
    float* out = (float*)d_out;

    __half *xh, *qkvh, *atth, *wqkvh, *wph;
    cudaGetSymbolAddress((void**)&xh,    g_xh4);
    cudaGetSymbolAddress((void**)&qkvh,  g_qkvh4);
    cudaGetSymbolAddress((void**)&atth,  g_atth4);
    cudaGetSymbolAddress((void**)&wqkvh, g_wqkvh4);
    cudaGetSymbolAddress((void**)&wph,   g_wph4);

    cudaFuncSetAttribute(gemm16_kernel<0>,
                         cudaFuncAttributeMaxDynamicSharedMemorySize, SMEM_GEMM);
    cudaFuncSetAttribute(gemm16_kernel<1>,
                         cudaFuncAttributeMaxDynamicSharedMemorySize, SMEM_GEMM);

    precompute_bm<<<(4 * NHEADS * 64 * 56 + 255) / 256, 256>>>(table);
    convert_gather_x<<<M_TOT * KDIM / 4 / 256, 256>>>(x);
    convert_weights<<<(NQKV + CDIM) * KDIM / 4 / 256, 256>>>(wqkv, wproj);

    gemm16_kernel<0><<<dim3(NQKV / TILE_MN, M_TOT / TILE_MN), 256, SMEM_GEMM>>>(
        xh, wqkvh, bqkv, qkvh, NQKV);
    attn_mma_kernel<<<dim3(NHEADS, WIN_TOT), 128>>>();
    gemm16_kernel<1><<<dim3(CDIM / TILE_MN, M_TOT / TILE_MN), 256, SMEM_GEMM>>>(
        atth, wph, bproj, out, 0);
}

// round 10
// speedup vs baseline: 7.3001x; 1.0805x over previous
#include <cuda_runtime.h>
#include <cuda_fp16.h>
#include <cstdint>

#define BATCH     16
#define IMG       56
#define CDIM      384
#define NHEADS    12
#define HDIM      32
#define NTOK      49
#define WIN_TOT   1024
#define M_TOT     50176
#define KDIM      384
#define NQKV      1152

#define TILE_MN   128
#define KC        64
#define NCHUNK    6
#define STAGE_BYTES 32768
#define SMEM_GEMM (3 * STAGE_BYTES)

// prologue job sizes (256-thread blocks)
#define NB_GATHER  (M_TOT * KDIM / 4 / 256)            // 18816
#define NB_WEIGHTS ((NQKV + CDIM) * KDIM / 4 / 256)    // 576
#define NB_BM      ((4 * NHEADS * 64 * 56 + 255) / 256) // 672

// fp16 scratch
__device__ uint4 g_xh4   [(size_t)M_TOT * KDIM  / 8];
__device__ uint4 g_qkvh4 [(size_t)M_TOT * NQKV  / 8];
__device__ uint4 g_atth4 [(size_t)M_TOT * CDIM  / 8];
__device__ uint4 g_wqkvh4[(size_t)NQKV  * KDIM  / 8];
__device__ uint4 g_wph4  [(size_t)CDIM  * KDIM  / 8];
__device__ float g_bm[4 * NHEADS * 64 * 56];

__device__ __forceinline__ uint32_t smem_u32(const void* p) {
    uint32_t a;
    asm("{ .reg .u64 t; cvta.to.shared.u64 t, %1; cvt.u32.u64 %0, t; }"
        : "=r"(a) : "l"(p));
    return a;
}

__device__ __forceinline__ int pix_offset(int m) {
    int win = m / 49;
    int tok = m - win * 49;
    int b  = win >> 6;
    int wi = win & 63;
    int wy = wi >> 3, wx = wi & 7;
    int ty = tok / 7, tx = tok - ty * 7;
    int h = wy * 7 + ty + 3; if (h >= IMG) h -= IMG;
    int w = wx * 7 + tx + 3; if (w >= IMG) w -= IMG;
    return ((b * IMG + h) * IMG + w) * CDIM;
}

#define CP_ASYNC16(dst, src) \
    asm volatile("cp.async.cg.shared.global [%0], [%1], 16;" :: "r"(dst), "l"(src))
#define CP_COMMIT() asm volatile("cp.async.commit_group;" ::: "memory")
template<int N> __device__ __forceinline__ void cp_wait() {
    asm volatile("cp.async.wait_group %0;" :: "n"(N) : "memory");
}

__device__ __forceinline__ void ldmatrix_x4(uint32_t addr, uint32_t& r0,
                                            uint32_t& r1, uint32_t& r2, uint32_t& r3) {
    asm volatile("ldmatrix.sync.aligned.m8n8.x4.shared.b16 {%0,%1,%2,%3}, [%4];"
                 : "=r"(r0), "=r"(r1), "=r"(r2), "=r"(r3) : "r"(addr));
}

__device__ __forceinline__ void ldmatrix_x4_trans(uint32_t addr, uint32_t& r0,
                                                  uint32_t& r1, uint32_t& r2, uint32_t& r3) {
    asm volatile("ldmatrix.sync.aligned.m8n8.x4.trans.shared.b16 {%0,%1,%2,%3}, [%4];"
                 : "=r"(r0), "=r"(r1), "=r"(r2), "=r"(r3) : "r"(addr));
}

__device__ __forceinline__ void mma16816(float* d, const uint32_t* a, const uint32_t* b) {
    asm volatile(
        "mma.sync.aligned.m16n8k16.row.col.f32.f16.f16.f32 "
        "{%0,%1,%2,%3}, {%4,%5,%6,%7}, {%8,%9}, {%0,%1,%2,%3};"
        : "+f"(d[0]), "+f"(d[1]), "+f"(d[2]), "+f"(d[3])
        : "r"(a[0]), "r"(a[1]), "r"(a[2]), "r"(a[3]), "r"(b[0]), "r"(b[1]));
}

__device__ __forceinline__ uint32_t packh2(float x, float y) {
    __half2 h = __floats2half2_rn(x, y);
    return *(uint32_t*)&h;
}

// ---------------------------------------------------------------------------
// Merged prologue: x gather+convert | weight converts | bias+mask precompute
// ---------------------------------------------------------------------------
__global__ __launch_bounds__(256) void prep_kernel(
    const float* __restrict__ x, const float* __restrict__ wqkv,
    const float* __restrict__ wproj, const float* __restrict__ table)
{
    int bx = blockIdx.x;
    if (bx < NB_GATHER) {
        __half* dst = (__half*)g_xh4;
        int i4 = bx * 256 + threadIdx.x;
        int m  = i4 / 96, k4 = (i4 % 96) * 4;
        float4 v = *(const float4*)(x + pix_offset(m) + k4);
        __half2 h0 = __floats2half2_rn(v.x, v.y);
        __half2 h1 = __floats2half2_rn(v.z, v.w);
        *(uint2*)(dst + (size_t)m * KDIM + k4) =
            make_uint2(*(uint32_t*)&h0, *(uint32_t*)&h1);
    } else if (bx < NB_GATHER + NB_WEIGHTS) {
        int i4 = ((bx - NB_GATHER) * 256 + threadIdx.x) * 4;
        const float* s;
        __half* d;
        if (i4 < NQKV * KDIM) {
            s = wqkv + i4;
            d = (__half*)g_wqkvh4 + i4;
        } else {
            s = wproj + (i4 - NQKV * KDIM);
            d = (__half*)g_wph4 + (i4 - NQKV * KDIM);
        }
        float4 v = *(const float4*)s;
        __half2 h0 = __floats2half2_rn(v.x, v.y);
        __half2 h1 = __floats2half2_rn(v.z, v.w);
        *(uint2*)d = make_uint2(*(uint32_t*)&h0, *(uint32_t*)&h1);
    } else {
        int idx = (bx - NB_GATHER - NB_WEIGHTS) * 256 + threadIdx.x;
        if (idx >= 4 * NHEADS * 64 * 56) return;
        int j = idx % 56;
        int t = idx / 56;
        int i = t % 64; t /= 64;
        int head = t % NHEADS;
        int cls = t / NHEADS;
        float v;
        if (j < 49) {
            int ie = (i < 49) ? i : 48;
            int iy = ie / 7, ix = ie % 7, jy = j / 7, jx = j % 7;
            float bias = table[((iy - jy + 6) * 13 + (ix - jx + 6)) * NHEADS + head];
            int clsh = cls >> 1, clsw = cls & 1;
            int hi = clsh ? ((iy < 4) ? 1 : 2) : 0;
            int wi = clsw ? ((ix < 4) ? 1 : 2) : 0;
            int hj = clsh ? ((jy < 4) ? 1 : 2) : 0;
            int wj = clsw ? ((jx < 4) ? 1 : 2) : 0;
            v = bias + (((hi * 3 + wi) != (hj * 3 + wj)) ? -100.0f : 0.0f);
        } else {
            v = -1e9f;
        }
        g_bm[idx] = v;
    }
}

// ---------------------------------------------------------------------------
// fp16 GEMM: 128 threads, 4 warps (2x2), warp tile 64x64, CTA tile 128x128.
// 3-stage cp.async pipeline, one barrier per chunk. 2 CTAs/SM.
// ---------------------------------------------------------------------------
template<int OUTMODE>
__global__ __launch_bounds__(128, 2) void gemm16_kernel(
    const __half* __restrict__ A, const __half* __restrict__ W,
    const float* __restrict__ bias, void* __restrict__ Out, int ldOut)
{
    extern __shared__ __align__(128) char smem[];
    uint32_t sb = smem_u32(smem);

    int tid  = threadIdx.x;
    int lane = tid & 31, wid = tid >> 5;
    int warpM = wid >> 1, warpN = wid & 1;          // 2 x 2 warps
    int tileM0 = blockIdx.y * TILE_MN;
    int n0 = blockIdx.x * TILE_MN;

    float acc[4][8][4] = {};                        // [mt][nt][reg]

    int rowA = warpM * 64 + (lane & 15);
    int kA   = (lane >> 4) * 8;
    uint32_t xa = (uint32_t)((rowA & 7) << 4);
    int rowB = warpN * 64 + (lane & 7) + ((lane >> 4) << 3);
    int kB   = ((lane >> 3) & 1) * 8;
    uint32_t xb = (uint32_t)((rowB & 7) << 4);

    // loader: 128 threads, 16B each; 8 iters cover a 1024-slot (16KB) tile
    int lr = tid >> 3;      // base row 0..15, +16 per iter
    int lc = tid & 7;

    const __half* Arow = A + (size_t)tileM0 * KDIM;
    const __half* Wrow = W + (size_t)n0 * KDIM;

    auto load_chunk = [&](int c) {
        uint32_t stage = sb + (uint32_t)((c % 3) * STAGE_BYTES);
        #pragma unroll
        for (int it = 0; it < 8; ++it) {
            int r = lr + it * 16;
            uint32_t off = ((uint32_t)(r * 128 + lc * 16)) ^ ((uint32_t)((r & 7) << 4));
            CP_ASYNC16(stage + off,          Arow + (size_t)r * KDIM + c * KC + lc * 8);
            CP_ASYNC16(stage + 16384 + off,  Wrow + (size_t)r * KDIM + c * KC + lc * 8);
        }
        CP_COMMIT();
    };

    load_chunk(0);
    load_chunk(1);

    #pragma unroll
    for (int c = 0; c < NCHUNK; ++c) {
        if (c == NCHUNK - 1) cp_wait<0>();
        else                 cp_wait<1>();
        __syncthreads();
        if (c + 2 < NCHUNK) load_chunk(c + 2);

        uint32_t sA = sb + (uint32_t)((c % 3) * STAGE_BYTES);
        uint32_t sB = sA + 16384;
        #pragma unroll
        for (int ks = 0; ks < 4; ++ks) {
            uint32_t a[4][4], b[8][2];
            #pragma unroll
            for (int mt = 0; mt < 4; ++mt) {
                uint32_t addr = sA + ((uint32_t)((rowA + mt * 16) * 128 + ks * 32 + kA * 2) ^ xa);
                ldmatrix_x4(addr, a[mt][0], a[mt][1], a[mt][2], a[mt][3]);
            }
            #pragma unroll
            for (int p = 0; p < 4; ++p) {
                uint32_t addr = sB + ((uint32_t)((rowB + p * 16) * 128 + ks * 32 + kB * 2) ^ xb);
                uint32_t r0, r1, r2, r3;
                ldmatrix_x4(addr, r0, r1, r2, r3);
                b[2 * p][0] = r0;     b[2 * p][1] = r1;
                b[2 * p + 1][0] = r2; b[2 * p + 1][1] = r3;
            }
            #pragma unroll
            for (int mt = 0; mt < 4; ++mt)
                #pragma unroll
                for (int nt = 0; nt < 8; ++nt)
                    mma16816(acc[mt][nt], a[mt], b[nt]);
        }
    }

    #pragma unroll
    for (int mt = 0; mt < 4; ++mt) {
        int m = tileM0 + warpM * 64 + mt * 16 + (lane >> 2);
        if (OUTMODE == 0) {
            __half* o0 = (__half*)Out + (size_t)m * ldOut;
            __half* o1 = (__half*)Out + (size_t)(m + 8) * ldOut;
            #pragma unroll
            for (int nt = 0; nt < 8; ++nt) {
                int n = n0 + warpN * 64 + nt * 8 + (lane & 3) * 2;
                float bx = __ldg(bias + n), by = __ldg(bias + n + 1);
                *(__half2*)(o0 + n) =
                    __floats2half2_rn(acc[mt][nt][0] + bx, acc[mt][nt][1] + by);
                *(__half2*)(o1 + n) =
                    __floats2half2_rn(acc[mt][nt][2] + bx, acc[mt][nt][3] + by);
            }
        } else {
            float* o0 = (float*)Out + pix_offset(m);
            float* o1 = (float*)Out + pix_offset(m + 8);
            #pragma unroll
            for (int nt = 0; nt < 8; ++nt) {
                int n = n0 + warpN * 64 + nt * 8 + (lane & 3) * 2;
                float bx = __ldg(bias + n), by = __ldg(bias + n + 1);
                *(float2*)(o0 + n) =
                    make_float2(acc[mt][nt][0] + bx, acc[mt][nt][1] + by);
                *(float2*)(o1 + n) =
                    make_float2(acc[mt][nt][2] + bx, acc[mt][nt][3] + by);
            }
        }
    }
}

// ---------------------------------------------------------------------------
// Tensor-core attention (R8/R9 — proven)
// ---------------------------------------------------------------------------
#define QK_STRIDE 40

__global__ __launch_bounds__(128) void attn_mma_kernel()
{
    __shared__ __align__(16) __half Qs[64 * QK_STRIDE];
    __shared__ __align__(16) __half Ks[64 * QK_STRIDE];
    __shared__ __align__(16) __half Vs[64 * QK_STRIDE];

    int head = blockIdx.x;
    int win  = blockIdx.y;
    int tid  = threadIdx.x;
    int lane = tid & 31, wid = tid >> 5;

    const __half* qkvh = (const __half*)g_qkvh4;
    size_t base = (size_t)win * NTOK * NQKV + head * HDIM;

    const __half2 sc2 = __floats2half2_rn(0.17677669529663687f, 0.17677669529663687f);
    #pragma unroll
    for (int f = tid; f < 256; f += 128) {
        int r = f >> 2, c = f & 3;
        uint4 qv = make_uint4(0, 0, 0, 0), kv = qv, vv = qv;
        if (r < NTOK) {
            const __half* p = qkvh + base + (size_t)r * NQKV + c * 8;
            qv = *(const uint4*)p;
            kv = *(const uint4*)(p + 384);
            vv = *(const uint4*)(p + 768);
            __half2* qh = (__half2*)&qv;
            #pragma unroll
            for (int t = 0; t < 4; ++t) qh[t] = __hmul2(qh[t], sc2);
        }
        *(uint4*)&Qs[r * QK_STRIDE + c * 8] = qv;
        *(uint4*)&Ks[r * QK_STRIDE + c * 8] = kv;
        *(uint4*)&Vs[r * QK_STRIDE + c * 8] = vv;
    }
    __syncthreads();

    uint32_t sQ = smem_u32(Qs), sK = smem_u32(Ks), sV = smem_u32(Vs);

    int gid = lane >> 2, tig = lane & 3;
    int rowbase = wid * 16;

    float s[7][4] = {};
    int aRow = rowbase + (lane & 15);
    int aK   = (lane >> 4) * 8;
    int bRow = (lane & 7) + ((lane >> 4) << 3);
    int bK   = ((lane >> 3) & 1) * 8;
    #pragma unroll
    for (int ks = 0; ks < 2; ++ks) {
        uint32_t a[4];
        ldmatrix_x4(sQ + (uint32_t)(aRow * QK_STRIDE + ks * 16 + aK) * 2,
                    a[0], a[1], a[2], a[3]);
        #pragma unroll
        for (int p = 0; p < 4; ++p) {
            uint32_t r0, r1, r2, r3;
            ldmatrix_x4(sK + (uint32_t)((p * 16 + bRow) * QK_STRIDE + ks * 16 + bK) * 2,
                        r0, r1, r2, r3);
            uint32_t b0[2] = {r0, r1}, b1[2] = {r2, r3};
            mma16816(s[2 * p], a, b0);
            if (p < 3) mma16816(s[2 * p + 1], a, b1);
        }
    }

    int r0 = rowbase + gid, r1 = r0 + 8;
    int wy = (win & 63) >> 3, wx = win & 7;
    int cls = ((wy == 7) ? 2 : 0) + ((wx == 7) ? 1 : 0);
    const float* bmBase = g_bm + (size_t)(cls * NHEADS + head) * 64 * 56;
    const float* bm0 = bmBase + r0 * 56 + tig * 2;
    const float* bm1 = bmBase + r1 * 56 + tig * 2;
    #pragma unroll
    for (int n = 0; n < 7; ++n) {
        float2 b0 = *(const float2*)(bm0 + n * 8);
        float2 b1 = *(const float2*)(bm1 + n * 8);
        s[n][0] += b0.x; s[n][1] += b0.y;
        s[n][2] += b1.x; s[n][3] += b1.y;
    }

    float mx0 = -1e30f, mx1 = -1e30f;
    #pragma unroll
    for (int n = 0; n < 7; ++n) {
        mx0 = fmaxf(mx0, fmaxf(s[n][0], s[n][1]));
        mx1 = fmaxf(mx1, fmaxf(s[n][2], s[n][3]));
    }
    mx0 = fmaxf(mx0, __shfl_xor_sync(0xffffffffu, mx0, 1));
    mx0 = fmaxf(mx0, __shfl_xor_sync(0xffffffffu, mx0, 2));
    mx1 = fmaxf(mx1, __shfl_xor_sync(0xffffffffu, mx1, 1));
    mx1 = fmaxf(mx1, __shfl_xor_sync(0xffffffffu, mx1, 2));

    float sm0 = 0.f, sm1 = 0.f;
    #pragma unroll
    for (int n = 0; n < 7; ++n) {
        s[n][0] = __expf(s[n][0] - mx0); sm0 += s[n][0];
        s[n][1] = __expf(s[n][1] - mx0); sm0 += s[n][1];
        s[n][2] = __expf(s[n][2] - mx1); sm1 += s[n][2];
        s[n][3] = __expf(s[n][3] - mx1); sm1 += s[n][3];
    }
    sm0 += __shfl_xor_sync(0xffffffffu, sm0, 1);
    sm0 += __shfl_xor_sync(0xffffffffu, sm0, 2);
    sm1 += __shfl_xor_sync(0xffffffffu, sm1, 1);
    sm1 += __shfl_xor_sync(0xffffffffu, sm1, 2);
    float inv0 = 1.0f / sm0, inv1 = 1.0f / sm1;

    uint32_t aP[4][4];
    #pragma unroll
    for (int kt = 0; kt < 4; ++kt) {
        aP[kt][0] = packh2(s[2 * kt][0], s[2 * kt][1]);
        aP[kt][1] = packh2(s[2 * kt][2], s[2 * kt][3]);
        if (kt < 3) {
            aP[kt][2] = packh2(s[2 * kt + 1][0], s[2 * kt + 1][1]);
            aP[kt][3] = packh2(s[2 * kt + 1][2], s[2 * kt + 1][3]);
        } else {
            aP[kt][2] = 0; aP[kt][3] = 0;
        }
    }

    float o[4][4] = {};
    int vRow = lane & 15;
    int vCol = (lane >> 4) << 3;
    #pragma unroll
    for (int kt = 0; kt < 4; ++kt) {
        #pragma unroll
        for (int np = 0; np < 2; ++np) {
            uint32_t r0v, r1v, r2v, r3v;
            uint32_t addr = sV + (uint32_t)((kt * 16 + vRow) * QK_STRIDE + np * 16 + vCol) * 2;
            ldmatrix_x4_trans(addr, r0v, r1v, r2v, r3v);
            uint32_t b0[2] = {r0v, r1v}, b1[2] = {r2v, r3v};
            mma16816(o[2 * np], aP[kt], b0);
            mma16816(o[2 * np + 1], aP[kt], b1);
        }
    }

    __half* att = (__half*)g_atth4;
    #pragma unroll
    for (int nt = 0; nt < 4; ++nt) {
        int col = head * HDIM + nt * 8 + tig * 2;
        if (r0 < NTOK)
            *(__half2*)(att + (size_t)(win * NTOK + r0) * CDIM + col) =
                __floats2half2_rn(o[nt][0] * inv0, o[nt][1] * inv0);
        if (r1 < NTOK)
            *(__half2*)(att + (size_t)(win * NTOK + r1) * CDIM + col) =
                __floats2half2_rn(o[nt][2] * inv1, o[nt][3] * inv1);
    }
}

extern "C" void kernel_launch(void* const* d_in, const int* in_sizes, int n_in,
                              void* d_out, int out_size) {
    const float* x     = (const float*)d_in[0];
    const float* wqkv  = (const float*)d_in[1];
    const float* bqkv  = (const float*)d_in[2];
    const float* wproj = (const float*)d_in[3];
    const float* bproj = (const float*)d_in[4];
    const float* table = (const float*)d_in[5];
    float* out = (float*)d_out;

    __half *xh, *qkvh, *atth, *wqkvh, *wph;
    cudaGetSymbolAddress((void**)&xh,    g_xh4);
    cudaGetSymbolAddress((void**)&qkvh,  g_qkvh4);
    cudaGetSymbolAddress((void**)&atth,  g_atth4);
    cudaGetSymbolAddress((void**)&wqkvh, g_wqkvh4);
    cudaGetSymbolAddress((void**)&wph,   g_wph4);

    cudaFuncSetAttribute(gemm16_kernel<0>,
                         cudaFuncAttributeMaxDynamicSharedMemorySize, SMEM_GEMM);
    cudaFuncSetAttribute(gemm16_kernel<1>,
                         cudaFuncAttributeMaxDynamicSharedMemorySize, SMEM_GEMM);

    prep_kernel<<<NB_GATHER + NB_WEIGHTS + NB_BM, 256>>>(x, wqkv, wproj, table);

    gemm16_kernel<0><<<dim3(NQKV / TILE_MN, M_TOT / TILE_MN), 128, SMEM_GEMM>>>(
        xh, wqkvh, bqkv, qkvh, NQKV);
    attn_mma_kernel<<<dim3(NHEADS, WIN_TOT), 128>>>();
    gemm16_kernel<1><<<dim3(CDIM / TILE_MN, M_TOT / TILE_MN), 128, SMEM_GEMM>>>(
        atth, wph, bproj, out, 0);
}